// round 8
// baseline (speedup 1.0000x reference)
#include <cuda_runtime.h>
#include <math.h>

#define BB 2
#define NN 2048
#define CC 256
#define HH 8
#define DHH 32
#define SCALE 0.17677669529663687f  // 1/sqrt(32)
#define CH 256                       // scan chunk size (NN/8)

typedef unsigned long long u64;

// ---- scratch ----
__device__ float g_qT[BB*HH*DHH*NN];   // [bh][d][n], pre-scaled
__device__ float g_kT[BB*HH*DHH*NN];   // [bh][d][n]
__device__ float g_v [BB*HH*NN*DHH];   // [bh][n][d]
__device__ float g_ctx[BB*NN*CC];
__device__ float g_pm[HH*NN];
__device__ float g_pinv[HH*NN];
__device__ float g_scanF[BB*HH*NN*DHH];  // fwd scan, then pos numerator (in-place)
__device__ float g_scanG[BB*HH*NN*DHH];  // bwd scan

// ---- f32x2 helpers ----
__device__ __forceinline__ void fma2(u64 &acc, u64 a, u64 b) {
    asm("fma.rn.f32x2 %0, %1, %2, %0;" : "+l"(acc) : "l"(a), "l"(b));
}
__device__ __forceinline__ u64 dup2(float x) {
    u64 r; asm("mov.b64 %0, {%1, %1};" : "=l"(r) : "f"(x)); return r;
}
__device__ __forceinline__ float2 unpack2(u64 v) {
    float2 r; asm("mov.b64 {%0, %1}, %2;" : "=f"(r.x), "=f"(r.y) : "l"(v)); return r;
}

// ============================================================
// 1) pos softmax row stats, closed form (geometric series)
// ============================================================
__global__ void pos_stats_kernel(const float* __restrict__ Wpos,
                                 const float* __restrict__ bpos) {
    int idx = blockIdx.x * blockDim.x + threadIdx.x;
    if (idx >= HH * NN) return;
    int h = idx / NN, i = idx - h * NN;
    float W0 = Wpos[h], W1 = Wpos[HH + h], bph = bpos[h];
    float apos = W0 + W1;
    float aneg = W1 - W0;
    float fi = (float)i, fM = (float)(NN - 1 - i);
    float mi = fmaxf(0.f, fmaxf(apos * fi, aneg * fM));

    float Sp;
    if (i == 0)            Sp = 0.f;
    else if (apos > 0.f)   Sp = __expf(apos * fi - mi) * expm1f(-apos * fi) / expm1f(-apos);
    else if (apos < 0.f)   Sp = __expf(apos - mi) * expm1f(apos * fi) / expm1f(apos);
    else                   Sp = fi * __expf(-mi);

    float Sn;
    if (i == NN - 1)       Sn = 0.f;
    else if (aneg > 0.f)   Sn = __expf(aneg * fM - mi) * expm1f(-aneg * fM) / expm1f(-aneg);
    else if (aneg < 0.f)   Sn = __expf(aneg - mi) * expm1f(aneg * fM) / expm1f(aneg);
    else                   Sn = fM * __expf(-mi);

    float den = __expf(-mi) + Sp + Sn;
    g_pm[idx]   = bph + mi;
    g_pinv[idx] = 1.f / den;
}

// ============================================================
// 2) QKV GEMM (f32x2) -> g_qT (scaled), g_kT, g_v
// ============================================================
__global__ void qkv_gemm_kernel(const float* __restrict__ x,
                                const float* __restrict__ Wqk,
                                const float* __restrict__ Wv) {
    __shared__ float As[16][68];      // [k][m], row 272B
    __shared__ float Bsd[16][128];    // [k][2*n] duplicated pairs
    int tid = threadIdx.x;
    int ty = tid >> 4, tx = tid & 15;
    int m0 = blockIdx.x * 64, n0 = blockIdx.y * 64;
    u64 acc2[2][4] = {};
    int arow = tid >> 2, acol = (tid & 3) * 4;
    int brow = tid >> 4, bcol = (tid & 15) * 4;

    for (int k0 = 0; k0 < 256; k0 += 16) {
        float4 av = *(const float4*)&x[(m0 + arow) * 256 + k0 + acol];
        As[acol + 0][arow] = av.x; As[acol + 1][arow] = av.y;
        As[acol + 2][arow] = av.z; As[acol + 3][arow] = av.w;
        int gc = n0 + bcol;
        float4 bv;
        if (gc < 512) bv = *(const float4*)&Wqk[(k0 + brow) * 512 + gc];
        else          bv = *(const float4*)&Wv[(k0 + brow) * 256 + gc - 512];
        *(float4*)&Bsd[brow][bcol * 2]     = make_float4(bv.x, bv.x, bv.y, bv.y);
        *(float4*)&Bsd[brow][bcol * 2 + 4] = make_float4(bv.z, bv.z, bv.w, bv.w);
        __syncthreads();
        #pragma unroll
        for (int kk = 0; kk < 16; kk++) {
            u64 a01 = *(const u64*)&As[kk][4 * ty];
            u64 a23 = *(const u64*)&As[kk][4 * ty + 2];
            ulonglong2 b01 = *(const ulonglong2*)&Bsd[kk][8 * tx];
            ulonglong2 b23 = *(const ulonglong2*)&Bsd[kk][8 * tx + 4];
            fma2(acc2[0][0], a01, b01.x); fma2(acc2[0][1], a01, b01.y);
            fma2(acc2[0][2], a01, b23.x); fma2(acc2[0][3], a01, b23.y);
            fma2(acc2[1][0], a23, b01.x); fma2(acc2[1][1], a23, b01.y);
            fma2(acc2[1][2], a23, b23.x); fma2(acc2[1][3], a23, b23.y);
        }
        __syncthreads();
    }
    #pragma unroll
    for (int p = 0; p < 2; p++) {
        #pragma unroll
        for (int j = 0; j < 4; j++) {
            float2 v2 = unpack2(acc2[p][j]);
            int c = n0 + 4 * tx + j;
            #pragma unroll
            for (int r = 0; r < 2; r++) {
                int m = m0 + 4 * ty + 2 * p + r;
                float v = r ? v2.y : v2.x;
                int b = m >> 11, n = m & (NN - 1);
                if (c < 256) {
                    int h = c >> 5, d = c & 31;
                    g_qT[((b * HH + h) * DHH + d) * NN + n] = v * SCALE;
                } else if (c < 512) {
                    int cc = c - 256; int h = cc >> 5, d = cc & 31;
                    g_kT[((b * HH + h) * DHH + d) * NN + n] = v;
                } else {
                    int cc = c - 512; int h = cc >> 5, d = cc & 31;
                    g_v[((b * HH + h) * NN + n) * DHH + d] = v;
                }
            }
        }
    }
}

// ============================================================
// 3) POS path: blocked-parallel exponential scans
// ============================================================
__global__ void __launch_bounds__(256) pos_scan_kernel(const float* __restrict__ Wpos,
                                                       const float* __restrict__ bpos) {
    __shared__ float TFs[8][32], TGs[8][32], AFs[8][32], DGs[8][32];

    int bh = blockIdx.x;
    int h = bh & (HH - 1);
    int tid = threadIdx.x;
    int w = tid >> 5, lane = tid & 31;
    float apos = Wpos[h] + Wpos[HH + h];
    float aneg = Wpos[HH + h] - Wpos[h];
    bool posg = apos > 0.f, negg = aneg > 0.f;
    float rhoF = posg ? 1.f : __expf(apos);
    float rhoG = negg ? 1.f : __expf(aneg);
    float wcF = posg ? -apos : 0.f;
    float wcG = negg ? -aneg : 0.f;
    float usG = negg ? 1.f : rhoG;

    const float* vp = g_v + bh * NN * DHH + lane;
    float* fo = g_scanF + bh * NN * DHH + lane;
    float* go = g_scanG + bh * NN * DHH + lane;
    int c0 = w * CH;

    float F = 0.f;
    for (int ib = c0; ib < c0 + CH; ib += 8) {
        float vb[8];
        #pragma unroll
        for (int u = 0; u < 8; u++) vb[u] = vp[(ib + u) * DHH];
        #pragma unroll
        for (int u = 0; u < 8; u++) {
            float uu = vb[u] * __expf(wcF * (float)(ib + u));
            F = rhoF * F + uu;
            fo[(ib + u) * DHH] = F;
        }
    }
    TFs[w][lane] = F;

    float G = 0.f;
    for (int ib = c0 + CH - 1; ib >= c0; ib -= 8) {
        float vb[8];
        #pragma unroll
        for (int u = 0; u < 8; u++) vb[u] = vp[(ib - u) * DHH];
        #pragma unroll
        for (int u = 0; u < 8; u++) {
            int i = ib - u;
            go[i * DHH] = G;
            float uu = usG * vb[u] * __expf(wcG * (float)(NN - 1 - i));
            G = rhoG * G + uu;
        }
    }
    TGs[w][lane] = G;
    __syncthreads();

    if (w == 0) {
        float fF = posg ? 1.f : __expf(apos * (float)CH);
        float A = 0.f;
        #pragma unroll
        for (int c = 0; c < 8; c++) { AFs[c][lane] = A; A = TFs[c][lane] + fF * A; }
    } else if (w == 1) {
        float fG = negg ? 1.f : __expf(aneg * (float)CH);
        float D = 0.f;
        #pragma unroll
        for (int c = 7; c >= 0; c--) { DGs[c][lane] = D; D = TGs[c][lane] + fG * D; }
    }
    __syncthreads();

    float A = AFs[w][lane];
    float D = DGs[w][lane];
    float pfc = posg ? 0.f : apos;
    float gfc = negg ? 0.f : aneg;
    float bph = bpos[h];
    float pp = fmaxf(apos, 0.f), pn = fmaxf(aneg, 0.f);
    const float* pmrow = g_pm + h * NN;
    int cend = c0 + CH;
    for (int i = c0; i < cend; i++) {
        float Fg = fo[i * DHH] + A * __expf(pfc * (float)(i - c0 + 1));
        float Gg = go[i * DHH] + D * __expf(gfc * (float)(cend - 1 - i));
        float pm = pmrow[i];
        float c1 = __expf(bph + pp * (float)i - pm);
        float c2 = __expf(bph + pn * (float)(NN - 1 - i) - pm);
        fo[i * DHH] = c1 * Fg + c2 * Gg;
    }
}

// ============================================================
// helper: load a [32][128] transposed tile into smem pad-132
// ============================================================
__device__ __forceinline__ void load_tile_T132(float (*dst)[132],
                                               const float* __restrict__ src,
                                               int n0, int tid) {
    #pragma unroll
    for (int r = 0; r < 4; r++) {
        int idx = tid + r * 256;
        int c  = idx & 15;
        int d  = (idx >> 4) & 31;
        int h2 = idx >> 9;
        int col = 4 * (c + 16 * h2);
        float4 v = *(const float4*)&src[d * NN + n0 + col];
        *(float4*)&dst[d][col] = v;
    }
}

// ============================================================
// 4) PATCH attention, software-pipelined (2 barriers/tile).
//    K double-buffered; V single-buffered (STS in exp phase).
// ============================================================
__global__ void __launch_bounds__(256, 2) attn_patch_kernel(const float* __restrict__ gating) {
    __shared__ float qs[32][132];    // [d][q]
    __shared__ float ks[2][32][36];  // [d][k] double-buffered
    __shared__ float vs[32][36];     // [k][d] single-buffered
    __shared__ float pT[32][132];    // [k][q]

    int tid = threadIdx.x;
    int ty = tid >> 4, tx = tid & 15;
    int qt = blockIdx.x, h = blockIdx.y, b = blockIdx.z;
    int bh = b * HH + h;
    int q0 = qt * 128;
    const float* qg = g_qT + bh * DHH * NN;
    const float* kg = g_kT + bh * DHH * NN;
    const float* vg = g_v  + bh * NN * DHH;

    load_tile_T132(qs, qg, q0, tid);

    int ldr = tid >> 3, ldc = tid & 7;
    const float* kgp = kg + ldr * NN + 4 * ldc;
    const float* vgp = vg + ldr * DHH + 4 * ldc;

    // prologue: K(0) -> smem buf0, V(0) -> regs
    float4 vvn_cur = *(const float4*)&vgp[0];
    *(float4*)&ks[0][ldr][4 * ldc] = *(const float4*)&kgp[0];
    __syncthreads();

    int dx = tid & 7, ks2 = (tid >> 3) & 1;
    u64 oaccP[4][4] = {};
    float l[8] = {};

    for (int kt = 0; kt < 64; kt++) {
        int buf = kt & 1;
        // prefetch tile kt+1 into registers
        float4 kvn, vvn_next;
        if (kt < 63) {
            kvn      = *(const float4*)&kgp[(kt + 1) * 32];
            vvn_next = *(const float4*)&vgp[(kt + 1) * 32 * DHH];
        }
        // ---- QK: 8q x 2k per thread (k cols 2tx, 2tx+1) ----
        u64 sacc[4][2] = {};
        #pragma unroll
        for (int d = 0; d < 32; d++) {
            ulonglong2 a0 = *(const ulonglong2*)&qs[d][8 * ty];
            ulonglong2 a1 = *(const ulonglong2*)&qs[d][8 * ty + 4];
            float2 kk2 = *(const float2*)&ks[buf][d][2 * tx];
            u64 b0 = dup2(kk2.x), b1 = dup2(kk2.y);
            fma2(sacc[0][0], a0.x, b0); fma2(sacc[0][1], a0.x, b1);
            fma2(sacc[1][0], a0.y, b0); fma2(sacc[1][1], a0.y, b1);
            fma2(sacc[2][0], a1.x, b0); fma2(sacc[2][1], a1.x, b1);
            fma2(sacc[3][0], a1.y, b0); fma2(sacc[3][1], a1.y, b1);
        }
        __syncthreads();   // A: PV(kt-1) finished reading pT and vs
        // ---- exp -> pT, l accum; stage next K, current V ----
        #pragma unroll
        for (int p = 0; p < 4; p++) {
            int i0 = 8 * ty + 2 * p;
            float2 s0 = unpack2(sacc[p][0]);
            float2 s1 = unpack2(sacc[p][1]);
            float e00 = __expf(s0.x), e01 = __expf(s0.y);
            float e10 = __expf(s1.x), e11 = __expf(s1.y);
            pT[2 * tx][i0]     = e00; pT[2 * tx][i0 + 1]     = e01;
            pT[2 * tx + 1][i0] = e10; pT[2 * tx + 1][i0 + 1] = e11;
            l[2 * p]     += e00 + e10;
            l[2 * p + 1] += e01 + e11;
        }
        *(float4*)&vs[ldr][4 * ldc] = vvn_cur;
        if (kt < 63) {
            *(float4*)&ks[buf ^ 1][ldr][4 * ldc] = kvn;
            vvn_cur = vvn_next;
        }
        __syncthreads();   // B: pT + vs ready
        // ---- PV (2-way split over k within tile) ----
        #pragma unroll
        for (int kk = 0; kk < 16; kk++) {
            int k = 2 * kk + ks2;
            ulonglong2 a0 = *(const ulonglong2*)&pT[k][8 * ty];
            ulonglong2 a1 = *(const ulonglong2*)&pT[k][8 * ty + 4];
            float4 bv = *(const float4*)&vs[k][4 * dx];
            u64 bd0 = dup2(bv.x), bd1 = dup2(bv.y), bd2 = dup2(bv.z), bd3 = dup2(bv.w);
            fma2(oaccP[0][0], a0.x, bd0); fma2(oaccP[0][1], a0.x, bd1);
            fma2(oaccP[0][2], a0.x, bd2); fma2(oaccP[0][3], a0.x, bd3);
            fma2(oaccP[1][0], a0.y, bd0); fma2(oaccP[1][1], a0.y, bd1);
            fma2(oaccP[1][2], a0.y, bd2); fma2(oaccP[1][3], a0.y, bd3);
            fma2(oaccP[2][0], a1.x, bd0); fma2(oaccP[2][1], a1.x, bd1);
            fma2(oaccP[2][2], a1.x, bd2); fma2(oaccP[2][3], a1.x, bd3);
            fma2(oaccP[3][0], a1.y, bd0); fma2(oaccP[3][1], a1.y, bd1);
            fma2(oaccP[3][2], a1.y, bd2); fma2(oaccP[3][3], a1.y, bd3);
        }
    }

    // ---- reduce l across 16 tx lanes ----
    #pragma unroll
    for (int o = 8; o; o >>= 1)
        #pragma unroll
        for (int r = 0; r < 8; r++)
            l[r] += __shfl_xor_sync(0xffffffffu, l[r], o);

    float gv = 1.f / (1.f + __expf(-gating[h]));
    float s1[8], s2[8];
    #pragma unroll
    for (int r = 0; r < 8; r++) {
        int row = q0 + 8 * ty + r;
        s1[r] = (1.f - gv) / l[r];
        s2[r] = gv * g_pinv[h * NN + row];
    }
    #pragma unroll
    for (int p = 0; p < 4; p++) {
        float o0a[4], o1a[4];
        #pragma unroll
        for (int j = 0; j < 4; j++) {
            float2 vp = unpack2(oaccP[p][j]);
            float o0 = s1[2 * p]     * vp.x;
            float o1 = s1[2 * p + 1] * vp.y;
            o0 += __shfl_xor_sync(0xffffffffu, o0, 8);
            o1 += __shfl_xor_sync(0xffffffffu, o1, 8);
            o0a[j] = o0; o1a[j] = o1;
        }
        if (tx < 8) {
            int row = q0 + 8 * ty + 2 * p;
            const float* pnp = &g_scanF[(bh * NN + row) * DHH + 4 * tx];
            float4 p0 = *(const float4*)pnp;
            float4 p1 = *(const float4*)(pnp + DHH);
            float a2 = s2[2 * p], b2 = s2[2 * p + 1];
            float4 r0 = make_float4(o0a[0] + a2 * p0.x, o0a[1] + a2 * p0.y,
                                    o0a[2] + a2 * p0.z, o0a[3] + a2 * p0.w);
            float4 r1 = make_float4(o1a[0] + b2 * p1.x, o1a[1] + b2 * p1.y,
                                    o1a[2] + b2 * p1.z, o1a[3] + b2 * p1.w);
            int col = h * 32 + 4 * tx;
            *(float4*)&g_ctx[(b * NN + row) * CC + col]     = r0;
            *(float4*)&g_ctx[(b * NN + row + 1) * CC + col] = r1;
        }
    }
}

// ============================================================
// 5) Output projection (f32x2)
// ============================================================
__global__ void proj_gemm_kernel(const float* __restrict__ Wp,
                                 const float* __restrict__ bp,
                                 float* __restrict__ out) {
    __shared__ float As[16][68];
    __shared__ float Bsd[16][128];
    int tid = threadIdx.x;
    int ty = tid >> 4, tx = tid & 15;
    int m0 = blockIdx.x * 64, n0 = blockIdx.y * 64;
    u64 acc2[2][4] = {};
    int arow = tid >> 2, acol = (tid & 3) * 4;
    int brow = tid >> 4, bcol = (tid & 15) * 4;

    for (int k0 = 0; k0 < 256; k0 += 16) {
        float4 av = *(const float4*)&g_ctx[(m0 + arow) * 256 + k0 + acol];
        As[acol + 0][arow] = av.x; As[acol + 1][arow] = av.y;
        As[acol + 2][arow] = av.z; As[acol + 3][arow] = av.w;
        float4 bv = *(const float4*)&Wp[(k0 + brow) * 256 + n0 + bcol];
        *(float4*)&Bsd[brow][bcol * 2]     = make_float4(bv.x, bv.x, bv.y, bv.y);
        *(float4*)&Bsd[brow][bcol * 2 + 4] = make_float4(bv.z, bv.z, bv.w, bv.w);
        __syncthreads();
        #pragma unroll
        for (int kk = 0; kk < 16; kk++) {
            u64 a01 = *(const u64*)&As[kk][4 * ty];
            u64 a23 = *(const u64*)&As[kk][4 * ty + 2];
            ulonglong2 b01 = *(const ulonglong2*)&Bsd[kk][8 * tx];
            ulonglong2 b23 = *(const ulonglong2*)&Bsd[kk][8 * tx + 4];
            fma2(acc2[0][0], a01, b01.x); fma2(acc2[0][1], a01, b01.y);
            fma2(acc2[0][2], a01, b23.x); fma2(acc2[0][3], a01, b23.y);
            fma2(acc2[1][0], a23, b01.x); fma2(acc2[1][1], a23, b01.y);
            fma2(acc2[1][2], a23, b23.x); fma2(acc2[1][3], a23, b23.y);
        }
        __syncthreads();
    }
    #pragma unroll
    for (int p = 0; p < 2; p++) {
        #pragma unroll
        for (int j = 0; j < 4; j++) {
            float2 v2 = unpack2(acc2[p][j]);
            int c = n0 + 4 * tx + j;
            int m = m0 + 4 * ty + 2 * p;
            out[m * 256 + c]       = v2.x + bp[c];
            out[(m + 1) * 256 + c] = v2.y + bp[c];
        }
    }
}

// ============================================================
extern "C" void kernel_launch(void* const* d_in, const int* in_sizes, int n_in,
                              void* d_out, int out_size) {
    const float* x     = (const float*)d_in[0];
    const float* Wqk   = (const float*)d_in[1];
    const float* Wv    = (const float*)d_in[2];
    const float* Wproj = (const float*)d_in[3];
    const float* bproj = (const float*)d_in[4];
    const float* Wpos  = (const float*)d_in[5];
    const float* bpos  = (const float*)d_in[6];
    const float* gate  = (const float*)d_in[7];
    float* out = (float*)d_out;

    pos_stats_kernel<<<(HH * NN + 255) / 256, 256>>>(Wpos, bpos);
    qkv_gemm_kernel<<<dim3(BB * NN / 64, 12), 256>>>(x, Wqk, Wv);
    pos_scan_kernel<<<BB * HH, 256>>>(Wpos, bpos);
    attn_patch_kernel<<<dim3(NN / 128, HH, BB), 256>>>(gate);
    proj_gemm_kernel<<<dim3(BB * NN / 64, 4), 256>>>(Wproj, bproj, out);
}

// round 9
// speedup vs baseline: 1.4585x; 1.4585x over previous
#include <cuda_runtime.h>
#include <math.h>

#define BB 2
#define NN 2048
#define CC 256
#define HH 8
#define DHH 32
#define SCALE 0.17677669529663687f  // 1/sqrt(32)
#define CH 256                       // scan chunk size (NN/8)

typedef unsigned long long u64;

// ---- scratch ----
__device__ float g_qT[BB*HH*DHH*NN];   // [bh][d][n], pre-scaled
__device__ float g_kT[BB*HH*DHH*NN];   // [bh][d][n]
__device__ float g_v [BB*HH*NN*DHH];   // [bh][n][d]
__device__ float g_ctx[BB*NN*CC];
__device__ float g_pm[HH*NN];
__device__ float g_pinv[HH*NN];
__device__ float g_scanF[BB*HH*NN*DHH];  // fwd scan, then pos numerator (in-place)
__device__ float g_scanG[BB*HH*NN*DHH];  // bwd scan

// ---- f32x2 helpers ----
__device__ __forceinline__ void fma2(u64 &acc, u64 a, u64 b) {
    asm("fma.rn.f32x2 %0, %1, %2, %0;" : "+l"(acc) : "l"(a), "l"(b));
}
__device__ __forceinline__ u64 dup2(float x) {
    u64 r; asm("mov.b64 %0, {%1, %1};" : "=l"(r) : "f"(x)); return r;
}
__device__ __forceinline__ float2 unpack2(u64 v) {
    float2 r; asm("mov.b64 {%0, %1}, %2;" : "=f"(r.x), "=f"(r.y) : "l"(v)); return r;
}

// ============================================================
// 1) pos softmax row stats, closed form (geometric series)
// ============================================================
__global__ void pos_stats_kernel(const float* __restrict__ Wpos,
                                 const float* __restrict__ bpos) {
    int idx = blockIdx.x * blockDim.x + threadIdx.x;
    if (idx >= HH * NN) return;
    int h = idx / NN, i = idx - h * NN;
    float W0 = Wpos[h], W1 = Wpos[HH + h], bph = bpos[h];
    float apos = W0 + W1;
    float aneg = W1 - W0;
    float fi = (float)i, fM = (float)(NN - 1 - i);
    float mi = fmaxf(0.f, fmaxf(apos * fi, aneg * fM));

    float Sp;
    if (i == 0)            Sp = 0.f;
    else if (apos > 0.f)   Sp = __expf(apos * fi - mi) * expm1f(-apos * fi) / expm1f(-apos);
    else if (apos < 0.f)   Sp = __expf(apos - mi) * expm1f(apos * fi) / expm1f(apos);
    else                   Sp = fi * __expf(-mi);

    float Sn;
    if (i == NN - 1)       Sn = 0.f;
    else if (aneg > 0.f)   Sn = __expf(aneg * fM - mi) * expm1f(-aneg * fM) / expm1f(-aneg);
    else if (aneg < 0.f)   Sn = __expf(aneg - mi) * expm1f(aneg * fM) / expm1f(aneg);
    else                   Sn = fM * __expf(-mi);

    float den = __expf(-mi) + Sp + Sn;
    g_pm[idx]   = bph + mi;
    g_pinv[idx] = 1.f / den;
}

// ============================================================
// 2) QKV GEMM (scalar FFMA — known-good) -> g_qT (scaled), g_kT, g_v
// ============================================================
__global__ void qkv_gemm_kernel(const float* __restrict__ x,
                                const float* __restrict__ Wqk,
                                const float* __restrict__ Wv) {
    __shared__ float As[16][64];
    __shared__ float Bs[16][64];
    int tid = threadIdx.x;
    int ty = tid >> 4, tx = tid & 15;
    int m0 = blockIdx.x * 64, n0 = blockIdx.y * 64;
    float acc[4][4] = {};
    int arow = tid >> 2, acol = (tid & 3) * 4;
    int brow = tid >> 4, bcol = (tid & 15) * 4;

    for (int k0 = 0; k0 < 256; k0 += 16) {
        float4 av = *(const float4*)&x[(m0 + arow) * 256 + k0 + acol];
        As[acol + 0][arow] = av.x; As[acol + 1][arow] = av.y;
        As[acol + 2][arow] = av.z; As[acol + 3][arow] = av.w;
        int gc = n0 + bcol;
        float4 bv;
        if (gc < 512) bv = *(const float4*)&Wqk[(k0 + brow) * 512 + gc];
        else          bv = *(const float4*)&Wv[(k0 + brow) * 256 + gc - 512];
        *(float4*)&Bs[brow][bcol] = bv;
        __syncthreads();
        #pragma unroll
        for (int kk = 0; kk < 16; kk++) {
            float4 a = *(float4*)&As[kk][4 * ty];
            float4 b = *(float4*)&Bs[kk][4 * tx];
            float aa[4] = {a.x, a.y, a.z, a.w};
            float bb[4] = {b.x, b.y, b.z, b.w};
            #pragma unroll
            for (int i = 0; i < 4; i++)
                #pragma unroll
                for (int j = 0; j < 4; j++)
                    acc[i][j] += aa[i] * bb[j];
        }
        __syncthreads();
    }
    #pragma unroll
    for (int i = 0; i < 4; i++) {
        int m = m0 + 4 * ty + i;
        int b = m >> 11, n = m & (NN - 1);
        #pragma unroll
        for (int j = 0; j < 4; j++) {
            int c = n0 + 4 * tx + j;
            float v = acc[i][j];
            if (c < 256) {
                int h = c >> 5, d = c & 31;
                g_qT[((b * HH + h) * DHH + d) * NN + n] = v * SCALE;
            } else if (c < 512) {
                int cc = c - 256; int h = cc >> 5, d = cc & 31;
                g_kT[((b * HH + h) * DHH + d) * NN + n] = v;
            } else {
                int cc = c - 512; int h = cc >> 5, d = cc & 31;
                g_v[((b * HH + h) * NN + n) * DHH + d] = v;
            }
        }
    }
}

// ============================================================
// 3) POS path: blocked-parallel exponential scans, 512 threads.
//    Warps 0-7: fwd scan of chunk w.  Warps 8-15: bwd scan of chunk w-8.
//    Carry scans, then phase-3 apply split across 16 warps (batched loads).
// ============================================================
__global__ void __launch_bounds__(512) pos_scan_kernel(const float* __restrict__ Wpos,
                                                       const float* __restrict__ bpos) {
    __shared__ float TFs[8][32], TGs[8][32], AFs[8][32], DGs[8][32];

    int bh = blockIdx.x;
    int h = bh & (HH - 1);
    int tid = threadIdx.x;
    int w = tid >> 5, lane = tid & 31;
    float apos = Wpos[h] + Wpos[HH + h];
    float aneg = Wpos[HH + h] - Wpos[h];
    bool posg = apos > 0.f, negg = aneg > 0.f;
    float rhoF = posg ? 1.f : __expf(apos);
    float rhoG = negg ? 1.f : __expf(aneg);
    float wcF = posg ? -apos : 0.f;
    float wcG = negg ? -aneg : 0.f;
    float usG = negg ? 1.f : rhoG;

    const float* vp = g_v + bh * NN * DHH + lane;
    float* fo = g_scanF + bh * NN * DHH + lane;
    float* go = g_scanG + bh * NN * DHH + lane;

    // ---- phase 1: F warps and G warps concurrent ----
    if (w < 8) {
        int c0 = w * CH;
        float F = 0.f;
        for (int ib = c0; ib < c0 + CH; ib += 8) {
            float vb[8];
            #pragma unroll
            for (int u = 0; u < 8; u++) vb[u] = vp[(ib + u) * DHH];
            #pragma unroll
            for (int u = 0; u < 8; u++) {
                float uu = vb[u] * __expf(wcF * (float)(ib + u));
                F = rhoF * F + uu;
                fo[(ib + u) * DHH] = F;
            }
        }
        TFs[w][lane] = F;
    } else {
        int c0 = (w - 8) * CH;
        float G = 0.f;
        for (int ib = c0 + CH - 1; ib >= c0; ib -= 8) {
            float vb[8];
            #pragma unroll
            for (int u = 0; u < 8; u++) vb[u] = vp[(ib - u) * DHH];
            #pragma unroll
            for (int u = 0; u < 8; u++) {
                int i = ib - u;
                go[i * DHH] = G;
                float uu = usG * vb[u] * __expf(wcG * (float)(NN - 1 - i));
                G = rhoG * G + uu;
            }
        }
        TGs[w - 8][lane] = G;
    }
    __syncthreads();

    // ---- phase 2: carry scans (per lane) ----
    if (w == 0) {
        float fF = posg ? 1.f : __expf(apos * (float)CH);
        float A = 0.f;
        #pragma unroll
        for (int c = 0; c < 8; c++) { AFs[c][lane] = A; A = TFs[c][lane] + fF * A; }
    } else if (w == 8) {
        float fG = negg ? 1.f : __expf(aneg * (float)CH);
        float D = 0.f;
        #pragma unroll
        for (int c = 7; c >= 0; c--) { DGs[c][lane] = D; D = TGs[c][lane] + fG * D; }
    }
    __syncthreads();

    // ---- phase 3: apply carries + row coeffs; warp w -> rows [w*128, w*128+128) ----
    int c = w >> 1;
    int c0 = c * CH;
    int cend = c0 + CH;
    int r0 = w * 128;
    float A = AFs[c][lane];
    float D = DGs[c][lane];
    float pfc = posg ? 0.f : apos;
    float gfc = negg ? 0.f : aneg;
    float bph = bpos[h];
    float pp = fmaxf(apos, 0.f), pn = fmaxf(aneg, 0.f);
    const float* pmrow = g_pm + h * NN;
    for (int ib = r0; ib < r0 + 128; ib += 8) {
        float fb[8], gb[8], pmb[8];
        #pragma unroll
        for (int u = 0; u < 8; u++) {
            fb[u]  = fo[(ib + u) * DHH];
            gb[u]  = go[(ib + u) * DHH];
            pmb[u] = pmrow[ib + u];
        }
        #pragma unroll
        for (int u = 0; u < 8; u++) {
            int i = ib + u;
            float Fg = fb[u] + A * __expf(pfc * (float)(i - c0 + 1));
            float Gg = gb[u] + D * __expf(gfc * (float)(cend - 1 - i));
            float c1 = __expf(bph + pp * (float)i - pmb[u]);
            float c2 = __expf(bph + pn * (float)(NN - 1 - i) - pmb[u]);
            fo[i * DHH] = c1 * Fg + c2 * Gg;
        }
    }
}

// ============================================================
// helper: load a [32][128] transposed tile into smem pad-132
// ============================================================
__device__ __forceinline__ void load_tile_T132(float (*dst)[132],
                                               const float* __restrict__ src,
                                               int n0, int tid) {
    #pragma unroll
    for (int r = 0; r < 4; r++) {
        int idx = tid + r * 256;
        int c  = idx & 15;
        int d  = (idx >> 4) & 31;
        int h2 = idx >> 9;
        int col = 4 * (c + 16 * h2);
        float4 v = *(const float4*)&src[d * NN + n0 + col];
        *(float4*)&dst[d][col] = v;
    }
}

// ============================================================
// 4) PATCH attention, software-pipelined (2 barriers/tile).
// ============================================================
__global__ void __launch_bounds__(256, 2) attn_patch_kernel(const float* __restrict__ gating) {
    __shared__ float qs[32][132];    // [d][q]
    __shared__ float ks[2][32][36];  // [d][k] double-buffered
    __shared__ float vs[32][36];     // [k][d] single-buffered
    __shared__ float pT[32][132];    // [k][q]

    int tid = threadIdx.x;
    int ty = tid >> 4, tx = tid & 15;
    int qt = blockIdx.x, h = blockIdx.y, b = blockIdx.z;
    int bh = b * HH + h;
    int q0 = qt * 128;
    const float* qg = g_qT + bh * DHH * NN;
    const float* kg = g_kT + bh * DHH * NN;
    const float* vg = g_v  + bh * NN * DHH;

    load_tile_T132(qs, qg, q0, tid);

    int ldr = tid >> 3, ldc = tid & 7;
    const float* kgp = kg + ldr * NN + 4 * ldc;
    const float* vgp = vg + ldr * DHH + 4 * ldc;

    float4 vvn_cur = *(const float4*)&vgp[0];
    *(float4*)&ks[0][ldr][4 * ldc] = *(const float4*)&kgp[0];
    __syncthreads();

    int dx = tid & 7, ks2 = (tid >> 3) & 1;
    u64 oaccP[4][4] = {};
    float l[8] = {};

    for (int kt = 0; kt < 64; kt++) {
        int buf = kt & 1;
        float4 kvn, vvn_next;
        if (kt < 63) {
            kvn      = *(const float4*)&kgp[(kt + 1) * 32];
            vvn_next = *(const float4*)&vgp[(kt + 1) * 32 * DHH];
        }
        u64 sacc[4][2] = {};
        #pragma unroll
        for (int d = 0; d < 32; d++) {
            ulonglong2 a0 = *(const ulonglong2*)&qs[d][8 * ty];
            ulonglong2 a1 = *(const ulonglong2*)&qs[d][8 * ty + 4];
            float2 kk2 = *(const float2*)&ks[buf][d][2 * tx];
            u64 b0 = dup2(kk2.x), b1 = dup2(kk2.y);
            fma2(sacc[0][0], a0.x, b0); fma2(sacc[0][1], a0.x, b1);
            fma2(sacc[1][0], a0.y, b0); fma2(sacc[1][1], a0.y, b1);
            fma2(sacc[2][0], a1.x, b0); fma2(sacc[2][1], a1.x, b1);
            fma2(sacc[3][0], a1.y, b0); fma2(sacc[3][1], a1.y, b1);
        }
        __syncthreads();
        #pragma unroll
        for (int p = 0; p < 4; p++) {
            int i0 = 8 * ty + 2 * p;
            float2 s0 = unpack2(sacc[p][0]);
            float2 s1 = unpack2(sacc[p][1]);
            float e00 = __expf(s0.x), e01 = __expf(s0.y);
            float e10 = __expf(s1.x), e11 = __expf(s1.y);
            pT[2 * tx][i0]     = e00; pT[2 * tx][i0 + 1]     = e01;
            pT[2 * tx + 1][i0] = e10; pT[2 * tx + 1][i0 + 1] = e11;
            l[2 * p]     += e00 + e10;
            l[2 * p + 1] += e01 + e11;
        }
        *(float4*)&vs[ldr][4 * ldc] = vvn_cur;
        if (kt < 63) {
            *(float4*)&ks[buf ^ 1][ldr][4 * ldc] = kvn;
            vvn_cur = vvn_next;
        }
        __syncthreads();
        #pragma unroll
        for (int kk = 0; kk < 16; kk++) {
            int k = 2 * kk + ks2;
            ulonglong2 a0 = *(const ulonglong2*)&pT[k][8 * ty];
            ulonglong2 a1 = *(const ulonglong2*)&pT[k][8 * ty + 4];
            float4 bv = *(const float4*)&vs[k][4 * dx];
            u64 bd0 = dup2(bv.x), bd1 = dup2(bv.y), bd2 = dup2(bv.z), bd3 = dup2(bv.w);
            fma2(oaccP[0][0], a0.x, bd0); fma2(oaccP[0][1], a0.x, bd1);
            fma2(oaccP[0][2], a0.x, bd2); fma2(oaccP[0][3], a0.x, bd3);
            fma2(oaccP[1][0], a0.y, bd0); fma2(oaccP[1][1], a0.y, bd1);
            fma2(oaccP[1][2], a0.y, bd2); fma2(oaccP[1][3], a0.y, bd3);
            fma2(oaccP[2][0], a1.x, bd0); fma2(oaccP[2][1], a1.x, bd1);
            fma2(oaccP[2][2], a1.x, bd2); fma2(oaccP[2][3], a1.x, bd3);
            fma2(oaccP[3][0], a1.y, bd0); fma2(oaccP[3][1], a1.y, bd1);
            fma2(oaccP[3][2], a1.y, bd2); fma2(oaccP[3][3], a1.y, bd3);
        }
    }

    #pragma unroll
    for (int o = 8; o; o >>= 1)
        #pragma unroll
        for (int r = 0; r < 8; r++)
            l[r] += __shfl_xor_sync(0xffffffffu, l[r], o);

    float gv = 1.f / (1.f + __expf(-gating[h]));
    float s1[8], s2[8];
    #pragma unroll
    for (int r = 0; r < 8; r++) {
        int row = q0 + 8 * ty + r;
        s1[r] = (1.f - gv) / l[r];
        s2[r] = gv * g_pinv[h * NN + row];
    }
    #pragma unroll
    for (int p = 0; p < 4; p++) {
        float o0a[4], o1a[4];
        #pragma unroll
        for (int j = 0; j < 4; j++) {
            float2 vp = unpack2(oaccP[p][j]);
            float o0 = s1[2 * p]     * vp.x;
            float o1 = s1[2 * p + 1] * vp.y;
            o0 += __shfl_xor_sync(0xffffffffu, o0, 8);
            o1 += __shfl_xor_sync(0xffffffffu, o1, 8);
            o0a[j] = o0; o1a[j] = o1;
        }
        if (tx < 8) {
            int row = q0 + 8 * ty + 2 * p;
            const float* pnp = &g_scanF[(bh * NN + row) * DHH + 4 * tx];
            float4 p0 = *(const float4*)pnp;
            float4 p1 = *(const float4*)(pnp + DHH);
            float a2 = s2[2 * p], b2 = s2[2 * p + 1];
            float4 r0 = make_float4(o0a[0] + a2 * p0.x, o0a[1] + a2 * p0.y,
                                    o0a[2] + a2 * p0.z, o0a[3] + a2 * p0.w);
            float4 r1 = make_float4(o1a[0] + b2 * p1.x, o1a[1] + b2 * p1.y,
                                    o1a[2] + b2 * p1.z, o1a[3] + b2 * p1.w);
            int col = h * 32 + 4 * tx;
            *(float4*)&g_ctx[(b * NN + row) * CC + col]     = r0;
            *(float4*)&g_ctx[(b * NN + row + 1) * CC + col] = r1;
        }
    }
}

// ============================================================
// 5) Output projection (scalar FFMA — known-good)
// ============================================================
__global__ void proj_gemm_kernel(const float* __restrict__ Wp,
                                 const float* __restrict__ bp,
                                 float* __restrict__ out) {
    __shared__ float As[16][64];
    __shared__ float Bs[16][64];
    int tid = threadIdx.x;
    int ty = tid >> 4, tx = tid & 15;
    int m0 = blockIdx.x * 64, n0 = blockIdx.y * 64;
    float acc[4][4] = {};
    int arow = tid >> 2, acol = (tid & 3) * 4;
    int brow = tid >> 4, bcol = (tid & 15) * 4;

    for (int k0 = 0; k0 < 256; k0 += 16) {
        float4 av = *(const float4*)&g_ctx[(m0 + arow) * 256 + k0 + acol];
        As[acol + 0][arow] = av.x; As[acol + 1][arow] = av.y;
        As[acol + 2][arow] = av.z; As[acol + 3][arow] = av.w;
        float4 bv = *(const float4*)&Wp[(k0 + brow) * 256 + n0 + bcol];
        *(float4*)&Bs[brow][bcol] = bv;
        __syncthreads();
        #pragma unroll
        for (int kk = 0; kk < 16; kk++) {
            float4 a = *(float4*)&As[kk][4 * ty];
            float4 b = *(float4*)&Bs[kk][4 * tx];
            float aa[4] = {a.x, a.y, a.z, a.w};
            float bb[4] = {b.x, b.y, b.z, b.w};
            #pragma unroll
            for (int i = 0; i < 4; i++)
                #pragma unroll
                for (int j = 0; j < 4; j++)
                    acc[i][j] += aa[i] * bb[j];
        }
        __syncthreads();
    }
    #pragma unroll
    for (int i = 0; i < 4; i++) {
        int m = m0 + 4 * ty + i;
        #pragma unroll
        for (int j = 0; j < 4; j++) {
            int c = n0 + 4 * tx + j;
            out[m * 256 + c] = acc[i][j] + bp[c];
        }
    }
}

// ============================================================
extern "C" void kernel_launch(void* const* d_in, const int* in_sizes, int n_in,
                              void* d_out, int out_size) {
    const float* x     = (const float*)d_in[0];
    const float* Wqk   = (const float*)d_in[1];
    const float* Wv    = (const float*)d_in[2];
    const float* Wproj = (const float*)d_in[3];
    const float* bproj = (const float*)d_in[4];
    const float* Wpos  = (const float*)d_in[5];
    const float* bpos  = (const float*)d_in[6];
    const float* gate  = (const float*)d_in[7];
    float* out = (float*)d_out;

    pos_stats_kernel<<<(HH * NN + 255) / 256, 256>>>(Wpos, bpos);
    qkv_gemm_kernel<<<dim3(BB * NN / 64, 12), 256>>>(x, Wqk, Wv);
    pos_scan_kernel<<<BB * HH, 512>>>(Wpos, bpos);
    attn_patch_kernel<<<dim3(NN / 128, HH, BB), 256>>>(gate);
    proj_gemm_kernel<<<dim3(BB * NN / 64, 4), 256>>>(Wproj, bproj, out);
}

// round 10
// speedup vs baseline: 1.4907x; 1.0221x over previous
#include <cuda_runtime.h>
#include <math.h>

#define BB 2
#define NN 2048
#define CC 256
#define HH 8
#define DHH 32
#define SCALE 0.17677669529663687f  // 1/sqrt(32)
#define CH 256                       // scan chunk size (NN/8)

typedef unsigned long long u64;

// ---- scratch ----
__device__ float g_qT[BB*HH*DHH*NN];   // [bh][d][n], pre-scaled
__device__ float g_kT[BB*HH*DHH*NN];   // [bh][d][n]
__device__ float g_v [BB*HH*NN*DHH];   // [bh][n][d]
__device__ float g_ctx[BB*NN*CC];
__device__ float g_pm[HH*NN];
__device__ float g_pinv[HH*NN];
__device__ float g_scanF[BB*HH*NN*DHH];  // fwd scan, then pos numerator (in-place)
__device__ float g_scanG[BB*HH*NN*DHH];  // bwd scan

// ---- f32x2 helpers ----
__device__ __forceinline__ void fma2(u64 &acc, u64 a, u64 b) {
    asm("fma.rn.f32x2 %0, %1, %2, %0;" : "+l"(acc) : "l"(a), "l"(b));
}
__device__ __forceinline__ u64 dup2(float x) {
    u64 r; asm("mov.b64 %0, {%1, %1};" : "=l"(r) : "f"(x)); return r;
}
__device__ __forceinline__ float2 unpack2(u64 v) {
    float2 r; asm("mov.b64 {%0, %1}, %2;" : "=f"(r.x), "=f"(r.y) : "l"(v)); return r;
}

// ============================================================
// 1) pos softmax row stats, closed form (geometric series)
// ============================================================
__global__ void pos_stats_kernel(const float* __restrict__ Wpos,
                                 const float* __restrict__ bpos) {
    int idx = blockIdx.x * blockDim.x + threadIdx.x;
    if (idx >= HH * NN) return;
    int h = idx / NN, i = idx - h * NN;
    float W0 = Wpos[h], W1 = Wpos[HH + h], bph = bpos[h];
    float apos = W0 + W1;
    float aneg = W1 - W0;
    float fi = (float)i, fM = (float)(NN - 1 - i);
    float mi = fmaxf(0.f, fmaxf(apos * fi, aneg * fM));

    float Sp;
    if (i == 0)            Sp = 0.f;
    else if (apos > 0.f)   Sp = __expf(apos * fi - mi) * expm1f(-apos * fi) / expm1f(-apos);
    else if (apos < 0.f)   Sp = __expf(apos - mi) * expm1f(apos * fi) / expm1f(apos);
    else                   Sp = fi * __expf(-mi);

    float Sn;
    if (i == NN - 1)       Sn = 0.f;
    else if (aneg > 0.f)   Sn = __expf(aneg * fM - mi) * expm1f(-aneg * fM) / expm1f(-aneg);
    else if (aneg < 0.f)   Sn = __expf(aneg - mi) * expm1f(aneg * fM) / expm1f(aneg);
    else                   Sn = fM * __expf(-mi);

    float den = __expf(-mi) + Sp + Sn;
    g_pm[idx]   = bph + mi;
    g_pinv[idx] = 1.f / den;
}

// ============================================================
// 2) QKV GEMM, f32x2 with register-dup, 128x64 tile, 8x4 micro
// ============================================================
__global__ void __launch_bounds__(256) qkv_gemm_kernel(const float* __restrict__ x,
                                const float* __restrict__ Wqk,
                                const float* __restrict__ Wv) {
    __shared__ float As[16][132];   // [k][m]
    __shared__ float Bs[16][68];    // [k][n]
    int tid = threadIdx.x;
    int ty = tid >> 4, tx = tid & 15;
    int m0 = blockIdx.x * 128, n0 = blockIdx.y * 64;
    u64 acc[4][4] = {};             // [row-pair][col]

    int arow = tid >> 1, akc = (tid & 1) * 8;     // A: 128 rows x 16 k
    int brow = tid >> 4, bcol = (tid & 15) * 4;   // B: 16 rows x 64 n

    for (int k0 = 0; k0 < 256; k0 += 16) {
        float4 a0 = *(const float4*)&x[(m0 + arow) * 256 + k0 + akc];
        float4 a1 = *(const float4*)&x[(m0 + arow) * 256 + k0 + akc + 4];
        As[akc + 0][arow] = a0.x; As[akc + 1][arow] = a0.y;
        As[akc + 2][arow] = a0.z; As[akc + 3][arow] = a0.w;
        As[akc + 4][arow] = a1.x; As[akc + 5][arow] = a1.y;
        As[akc + 6][arow] = a1.z; As[akc + 7][arow] = a1.w;
        int gc = n0 + bcol;
        float4 bv;
        if (gc < 512) bv = *(const float4*)&Wqk[(k0 + brow) * 512 + gc];
        else          bv = *(const float4*)&Wv[(k0 + brow) * 256 + gc - 512];
        *(float4*)&Bs[brow][bcol] = bv;
        __syncthreads();
        #pragma unroll
        for (int kk = 0; kk < 16; kk++) {
            ulonglong2 ap0 = *(const ulonglong2*)&As[kk][8 * ty];
            ulonglong2 ap1 = *(const ulonglong2*)&As[kk][8 * ty + 4];
            float4 bv4 = *(const float4*)&Bs[kk][4 * tx];
            u64 b0 = dup2(bv4.x), b1 = dup2(bv4.y), b2 = dup2(bv4.z), b3 = dup2(bv4.w);
            fma2(acc[0][0], ap0.x, b0); fma2(acc[0][1], ap0.x, b1);
            fma2(acc[0][2], ap0.x, b2); fma2(acc[0][3], ap0.x, b3);
            fma2(acc[1][0], ap0.y, b0); fma2(acc[1][1], ap0.y, b1);
            fma2(acc[1][2], ap0.y, b2); fma2(acc[1][3], ap0.y, b3);
            fma2(acc[2][0], ap1.x, b0); fma2(acc[2][1], ap1.x, b1);
            fma2(acc[2][2], ap1.x, b2); fma2(acc[2][3], ap1.x, b3);
            fma2(acc[3][0], ap1.y, b0); fma2(acc[3][1], ap1.y, b1);
            fma2(acc[3][2], ap1.y, b2); fma2(acc[3][3], ap1.y, b3);
        }
        __syncthreads();
    }
    #pragma unroll
    for (int p = 0; p < 4; p++) {
        #pragma unroll
        for (int j = 0; j < 4; j++) {
            float2 v2 = unpack2(acc[p][j]);
            int c = n0 + 4 * tx + j;
            #pragma unroll
            for (int r = 0; r < 2; r++) {
                int m = m0 + 8 * ty + 2 * p + r;
                float v = r ? v2.y : v2.x;
                int b = m >> 11, n = m & (NN - 1);
                if (c < 256) {
                    int h = c >> 5, d = c & 31;
                    g_qT[((b * HH + h) * DHH + d) * NN + n] = v * SCALE;
                } else if (c < 512) {
                    int cc = c - 256; int h = cc >> 5, d = cc & 31;
                    g_kT[((b * HH + h) * DHH + d) * NN + n] = v;
                } else {
                    int cc = c - 512; int h = cc >> 5, d = cc & 31;
                    g_v[((b * HH + h) * NN + n) * DHH + d] = v;
                }
            }
        }
    }
}

// ============================================================
// 3) POS path: blocked-parallel exponential scans, 512 threads
// ============================================================
__global__ void __launch_bounds__(512) pos_scan_kernel(const float* __restrict__ Wpos,
                                                       const float* __restrict__ bpos) {
    __shared__ float TFs[8][32], TGs[8][32], AFs[8][32], DGs[8][32];

    int bh = blockIdx.x;
    int h = bh & (HH - 1);
    int tid = threadIdx.x;
    int w = tid >> 5, lane = tid & 31;
    float apos = Wpos[h] + Wpos[HH + h];
    float aneg = Wpos[HH + h] - Wpos[h];
    bool posg = apos > 0.f, negg = aneg > 0.f;
    float rhoF = posg ? 1.f : __expf(apos);
    float rhoG = negg ? 1.f : __expf(aneg);
    float wcF = posg ? -apos : 0.f;
    float wcG = negg ? -aneg : 0.f;
    float usG = negg ? 1.f : rhoG;

    const float* vp = g_v + bh * NN * DHH + lane;
    float* fo = g_scanF + bh * NN * DHH + lane;
    float* go = g_scanG + bh * NN * DHH + lane;

    if (w < 8) {
        int c0 = w * CH;
        float F = 0.f;
        for (int ib = c0; ib < c0 + CH; ib += 8) {
            float vb[8];
            #pragma unroll
            for (int u = 0; u < 8; u++) vb[u] = vp[(ib + u) * DHH];
            #pragma unroll
            for (int u = 0; u < 8; u++) {
                float uu = vb[u] * __expf(wcF * (float)(ib + u));
                F = rhoF * F + uu;
                fo[(ib + u) * DHH] = F;
            }
        }
        TFs[w][lane] = F;
    } else {
        int c0 = (w - 8) * CH;
        float G = 0.f;
        for (int ib = c0 + CH - 1; ib >= c0; ib -= 8) {
            float vb[8];
            #pragma unroll
            for (int u = 0; u < 8; u++) vb[u] = vp[(ib - u) * DHH];
            #pragma unroll
            for (int u = 0; u < 8; u++) {
                int i = ib - u;
                go[i * DHH] = G;
                float uu = usG * vb[u] * __expf(wcG * (float)(NN - 1 - i));
                G = rhoG * G + uu;
            }
        }
        TGs[w - 8][lane] = G;
    }
    __syncthreads();

    if (w == 0) {
        float fF = posg ? 1.f : __expf(apos * (float)CH);
        float A = 0.f;
        #pragma unroll
        for (int c = 0; c < 8; c++) { AFs[c][lane] = A; A = TFs[c][lane] + fF * A; }
    } else if (w == 8) {
        float fG = negg ? 1.f : __expf(aneg * (float)CH);
        float D = 0.f;
        #pragma unroll
        for (int c = 7; c >= 0; c--) { DGs[c][lane] = D; D = TGs[c][lane] + fG * D; }
    }
    __syncthreads();

    int c = w >> 1;
    int c0 = c * CH;
    int cend = c0 + CH;
    int r0 = w * 128;
    float A = AFs[c][lane];
    float D = DGs[c][lane];
    float pfc = posg ? 0.f : apos;
    float gfc = negg ? 0.f : aneg;
    float bph = bpos[h];
    float pp = fmaxf(apos, 0.f), pn = fmaxf(aneg, 0.f);
    const float* pmrow = g_pm + h * NN;
    for (int ib = r0; ib < r0 + 128; ib += 8) {
        float fb[8], gb[8], pmb[8];
        #pragma unroll
        for (int u = 0; u < 8; u++) {
            fb[u]  = fo[(ib + u) * DHH];
            gb[u]  = go[(ib + u) * DHH];
            pmb[u] = pmrow[ib + u];
        }
        #pragma unroll
        for (int u = 0; u < 8; u++) {
            int i = ib + u;
            float Fg = fb[u] + A * __expf(pfc * (float)(i - c0 + 1));
            float Gg = gb[u] + D * __expf(gfc * (float)(cend - 1 - i));
            float c1 = __expf(bph + pp * (float)i - pmb[u]);
            float c2 = __expf(bph + pn * (float)(NN - 1 - i) - pmb[u]);
            fo[i * DHH] = c1 * Fg + c2 * Gg;
        }
    }
}

// ============================================================
// helper: load a [32][128] transposed tile into smem pad-132
// ============================================================
__device__ __forceinline__ void load_tile_T132(float (*dst)[132],
                                               const float* __restrict__ src,
                                               int n0, int tid) {
    #pragma unroll
    for (int r = 0; r < 4; r++) {
        int idx = tid + r * 256;
        int c  = idx & 15;
        int d  = (idx >> 4) & 31;
        int h2 = idx >> 9;
        int col = 4 * (c + 16 * h2);
        float4 v = *(const float4*)&src[d * NN + n0 + col];
        *(float4*)&dst[d][col] = v;
    }
}

// ============================================================
// 4) PATCH attention, software-pipelined (2 barriers/tile).
// ============================================================
__global__ void __launch_bounds__(256, 2) attn_patch_kernel(const float* __restrict__ gating) {
    __shared__ float qs[32][132];    // [d][q]
    __shared__ float ks[2][32][36];  // [d][k] double-buffered
    __shared__ float vs[32][36];     // [k][d] single-buffered
    __shared__ float pT[32][132];    // [k][q]

    int tid = threadIdx.x;
    int ty = tid >> 4, tx = tid & 15;
    int qt = blockIdx.x, h = blockIdx.y, b = blockIdx.z;
    int bh = b * HH + h;
    int q0 = qt * 128;
    const float* qg = g_qT + bh * DHH * NN;
    const float* kg = g_kT + bh * DHH * NN;
    const float* vg = g_v  + bh * NN * DHH;

    load_tile_T132(qs, qg, q0, tid);

    int ldr = tid >> 3, ldc = tid & 7;
    const float* kgp = kg + ldr * NN + 4 * ldc;
    const float* vgp = vg + ldr * DHH + 4 * ldc;

    float4 vvn_cur = *(const float4*)&vgp[0];
    *(float4*)&ks[0][ldr][4 * ldc] = *(const float4*)&kgp[0];
    __syncthreads();

    int dx = tid & 7, ks2 = (tid >> 3) & 1;
    u64 oaccP[4][4] = {};
    float l[8] = {};

    for (int kt = 0; kt < 64; kt++) {
        int buf = kt & 1;
        float4 kvn, vvn_next;
        if (kt < 63) {
            kvn      = *(const float4*)&kgp[(kt + 1) * 32];
            vvn_next = *(const float4*)&vgp[(kt + 1) * 32 * DHH];
        }
        u64 sacc[4][2] = {};
        #pragma unroll
        for (int d = 0; d < 32; d++) {
            ulonglong2 a0 = *(const ulonglong2*)&qs[d][8 * ty];
            ulonglong2 a1 = *(const ulonglong2*)&qs[d][8 * ty + 4];
            float2 kk2 = *(const float2*)&ks[buf][d][2 * tx];
            u64 b0 = dup2(kk2.x), b1 = dup2(kk2.y);
            fma2(sacc[0][0], a0.x, b0); fma2(sacc[0][1], a0.x, b1);
            fma2(sacc[1][0], a0.y, b0); fma2(sacc[1][1], a0.y, b1);
            fma2(sacc[2][0], a1.x, b0); fma2(sacc[2][1], a1.x, b1);
            fma2(sacc[3][0], a1.y, b0); fma2(sacc[3][1], a1.y, b1);
        }
        __syncthreads();
        #pragma unroll
        for (int p = 0; p < 4; p++) {
            int i0 = 8 * ty + 2 * p;
            float2 s0 = unpack2(sacc[p][0]);
            float2 s1 = unpack2(sacc[p][1]);
            float e00 = __expf(s0.x), e01 = __expf(s0.y);
            float e10 = __expf(s1.x), e11 = __expf(s1.y);
            pT[2 * tx][i0]     = e00; pT[2 * tx][i0 + 1]     = e01;
            pT[2 * tx + 1][i0] = e10; pT[2 * tx + 1][i0 + 1] = e11;
            l[2 * p]     += e00 + e10;
            l[2 * p + 1] += e01 + e11;
        }
        *(float4*)&vs[ldr][4 * ldc] = vvn_cur;
        if (kt < 63) {
            *(float4*)&ks[buf ^ 1][ldr][4 * ldc] = kvn;
            vvn_cur = vvn_next;
        }
        __syncthreads();
        #pragma unroll
        for (int kk = 0; kk < 16; kk++) {
            int k = 2 * kk + ks2;
            ulonglong2 a0 = *(const ulonglong2*)&pT[k][8 * ty];
            ulonglong2 a1 = *(const ulonglong2*)&pT[k][8 * ty + 4];
            float4 bv = *(const float4*)&vs[k][4 * dx];
            u64 bd0 = dup2(bv.x), bd1 = dup2(bv.y), bd2 = dup2(bv.z), bd3 = dup2(bv.w);
            fma2(oaccP[0][0], a0.x, bd0); fma2(oaccP[0][1], a0.x, bd1);
            fma2(oaccP[0][2], a0.x, bd2); fma2(oaccP[0][3], a0.x, bd3);
            fma2(oaccP[1][0], a0.y, bd0); fma2(oaccP[1][1], a0.y, bd1);
            fma2(oaccP[1][2], a0.y, bd2); fma2(oaccP[1][3], a0.y, bd3);
            fma2(oaccP[2][0], a1.x, bd0); fma2(oaccP[2][1], a1.x, bd1);
            fma2(oaccP[2][2], a1.x, bd2); fma2(oaccP[2][3], a1.x, bd3);
            fma2(oaccP[3][0], a1.y, bd0); fma2(oaccP[3][1], a1.y, bd1);
            fma2(oaccP[3][2], a1.y, bd2); fma2(oaccP[3][3], a1.y, bd3);
        }
    }

    #pragma unroll
    for (int o = 8; o; o >>= 1)
        #pragma unroll
        for (int r = 0; r < 8; r++)
            l[r] += __shfl_xor_sync(0xffffffffu, l[r], o);

    float gv = 1.f / (1.f + __expf(-gating[h]));
    float s1[8], s2[8];
    #pragma unroll
    for (int r = 0; r < 8; r++) {
        int row = q0 + 8 * ty + r;
        s1[r] = (1.f - gv) / l[r];
        s2[r] = gv * g_pinv[h * NN + row];
    }
    #pragma unroll
    for (int p = 0; p < 4; p++) {
        float o0a[4], o1a[4];
        #pragma unroll
        for (int j = 0; j < 4; j++) {
            float2 vp = unpack2(oaccP[p][j]);
            float o0 = s1[2 * p]     * vp.x;
            float o1 = s1[2 * p + 1] * vp.y;
            o0 += __shfl_xor_sync(0xffffffffu, o0, 8);
            o1 += __shfl_xor_sync(0xffffffffu, o1, 8);
            o0a[j] = o0; o1a[j] = o1;
        }
        if (tx < 8) {
            int row = q0 + 8 * ty + 2 * p;
            const float* pnp = &g_scanF[(bh * NN + row) * DHH + 4 * tx];
            float4 p0 = *(const float4*)pnp;
            float4 p1 = *(const float4*)(pnp + DHH);
            float a2 = s2[2 * p], b2 = s2[2 * p + 1];
            float4 r0 = make_float4(o0a[0] + a2 * p0.x, o0a[1] + a2 * p0.y,
                                    o0a[2] + a2 * p0.z, o0a[3] + a2 * p0.w);
            float4 r1 = make_float4(o1a[0] + b2 * p1.x, o1a[1] + b2 * p1.y,
                                    o1a[2] + b2 * p1.z, o1a[3] + b2 * p1.w);
            int col = h * 32 + 4 * tx;
            *(float4*)&g_ctx[(b * NN + row) * CC + col]     = r0;
            *(float4*)&g_ctx[(b * NN + row + 1) * CC + col] = r1;
        }
    }
}

// ============================================================
// 5) Output projection, f32x2 register-dup, 128x64 tile
// ============================================================
__global__ void __launch_bounds__(256) proj_gemm_kernel(const float* __restrict__ Wp,
                                 const float* __restrict__ bp,
                                 float* __restrict__ out) {
    __shared__ float As[16][132];
    __shared__ float Bs[16][68];
    int tid = threadIdx.x;
    int ty = tid >> 4, tx = tid & 15;
    int m0 = blockIdx.x * 128, n0 = blockIdx.y * 64;
    u64 acc[4][4] = {};

    int arow = tid >> 1, akc = (tid & 1) * 8;
    int brow = tid >> 4, bcol = (tid & 15) * 4;

    for (int k0 = 0; k0 < 256; k0 += 16) {
        float4 a0 = *(const float4*)&g_ctx[(m0 + arow) * 256 + k0 + akc];
        float4 a1 = *(const float4*)&g_ctx[(m0 + arow) * 256 + k0 + akc + 4];
        As[akc + 0][arow] = a0.x; As[akc + 1][arow] = a0.y;
        As[akc + 2][arow] = a0.z; As[akc + 3][arow] = a0.w;
        As[akc + 4][arow] = a1.x; As[akc + 5][arow] = a1.y;
        As[akc + 6][arow] = a1.z; As[akc + 7][arow] = a1.w;
        *(float4*)&Bs[brow][bcol] = *(const float4*)&Wp[(k0 + brow) * 256 + n0 + bcol];
        __syncthreads();
        #pragma unroll
        for (int kk = 0; kk < 16; kk++) {
            ulonglong2 ap0 = *(const ulonglong2*)&As[kk][8 * ty];
            ulonglong2 ap1 = *(const ulonglong2*)&As[kk][8 * ty + 4];
            float4 bv4 = *(const float4*)&Bs[kk][4 * tx];
            u64 b0 = dup2(bv4.x), b1 = dup2(bv4.y), b2 = dup2(bv4.z), b3 = dup2(bv4.w);
            fma2(acc[0][0], ap0.x, b0); fma2(acc[0][1], ap0.x, b1);
            fma2(acc[0][2], ap0.x, b2); fma2(acc[0][3], ap0.x, b3);
            fma2(acc[1][0], ap0.y, b0); fma2(acc[1][1], ap0.y, b1);
            fma2(acc[1][2], ap0.y, b2); fma2(acc[1][3], ap0.y, b3);
            fma2(acc[2][0], ap1.x, b0); fma2(acc[2][1], ap1.x, b1);
            fma2(acc[2][2], ap1.x, b2); fma2(acc[2][3], ap1.x, b3);
            fma2(acc[3][0], ap1.y, b0); fma2(acc[3][1], ap1.y, b1);
            fma2(acc[3][2], ap1.y, b2); fma2(acc[3][3], ap1.y, b3);
        }
        __syncthreads();
    }
    #pragma unroll
    for (int p = 0; p < 4; p++) {
        #pragma unroll
        for (int j = 0; j < 4; j++) {
            float2 v2 = unpack2(acc[p][j]);
            int c = n0 + 4 * tx + j;
            int m = m0 + 8 * ty + 2 * p;
            out[m * 256 + c]       = v2.x + bp[c];
            out[(m + 1) * 256 + c] = v2.y + bp[c];
        }
    }
}

// ============================================================
extern "C" void kernel_launch(void* const* d_in, const int* in_sizes, int n_in,
                              void* d_out, int out_size) {
    const float* x     = (const float*)d_in[0];
    const float* Wqk   = (const float*)d_in[1];
    const float* Wv    = (const float*)d_in[2];
    const float* Wproj = (const float*)d_in[3];
    const float* bproj = (const float*)d_in[4];
    const float* Wpos  = (const float*)d_in[5];
    const float* bpos  = (const float*)d_in[6];
    const float* gate  = (const float*)d_in[7];
    float* out = (float*)d_out;

    pos_stats_kernel<<<(HH * NN + 255) / 256, 256>>>(Wpos, bpos);
    qkv_gemm_kernel<<<dim3(BB * NN / 128, 12), 256>>>(x, Wqk, Wv);
    pos_scan_kernel<<<BB * HH, 512>>>(Wpos, bpos);
    attn_patch_kernel<<<dim3(NN / 128, HH, BB), 256>>>(gate);
    proj_gemm_kernel<<<dim3(BB * NN / 128, 4), 256>>>(Wproj, bproj, out);
}

// round 12
// speedup vs baseline: 2.4383x; 1.6356x over previous
#include <cuda_runtime.h>
#include <cuda_bf16.h>
#include <math.h>

#define BB 2
#define NN 2048
#define CC 256
#define HH 8
#define DHH 32
#define SCALE 0.17677669529663687f  // 1/sqrt(32)
#define CH 256                       // scan chunk size (NN/8)

typedef unsigned long long u64;
typedef unsigned u32;

// ---- scratch ----
__device__ __nv_bfloat16 g_qbh[BB*HH*NN*DHH];  // [bh][n][d] hi, pre-scaled
__device__ __nv_bfloat16 g_qbl[BB*HH*NN*DHH];  // lo
__device__ __nv_bfloat16 g_kbh[BB*HH*NN*DHH];  // [bh][n][d] hi
__device__ __nv_bfloat16 g_kbl[BB*HH*NN*DHH];
__device__ __nv_bfloat16 g_vth[BB*HH*DHH*NN];  // [bh][d][n] hi (transposed)
__device__ __nv_bfloat16 g_vtl[BB*HH*DHH*NN];
__device__ float g_v [BB*HH*NN*DHH];           // [bh][n][d] f32 (scan input)
__device__ float g_ctx[BB*NN*CC];
__device__ float g_pm[HH*NN];
__device__ float g_pinv[HH*NN];
__device__ float g_scanF[BB*HH*NN*DHH];
__device__ float g_scanG[BB*HH*NN*DHH];

// ---- f32x2 helpers ----
__device__ __forceinline__ void fma2(u64 &acc, u64 a, u64 b) {
    asm("fma.rn.f32x2 %0, %1, %2, %0;" : "+l"(acc) : "l"(a), "l"(b));
}
__device__ __forceinline__ u64 dup2(float x) {
    u64 r; asm("mov.b64 %0, {%1, %1};" : "=l"(r) : "f"(x)); return r;
}
__device__ __forceinline__ float2 unpack2(u64 v) {
    float2 r; asm("mov.b64 {%0, %1}, %2;" : "=f"(r.x), "=f"(r.y) : "l"(v)); return r;
}

// ---- mma.sync bf16 (sm_80+ PTX; valid at compute_103) ----
__device__ __forceinline__ void mma_bf16(float d[4], const u32 a[4], u32 b0, u32 b1) {
    asm volatile(
        "mma.sync.aligned.m16n8k16.row.col.f32.bf16.bf16.f32 "
        "{%0,%1,%2,%3}, {%4,%5,%6,%7}, {%8,%9}, {%0,%1,%2,%3};"
        : "+f"(d[0]), "+f"(d[1]), "+f"(d[2]), "+f"(d[3])
        : "r"(a[0]), "r"(a[1]), "r"(a[2]), "r"(a[3]), "r"(b0), "r"(b1));
}
__device__ __forceinline__ u32 packbf2(float lo, float hi) {
    __nv_bfloat162 v = __floats2bfloat162_rn(lo, hi);
    return *(u32*)&v;
}

// ============================================================
// 1) pos softmax row stats, closed form (geometric series)
// ============================================================
__global__ void pos_stats_kernel(const float* __restrict__ Wpos,
                                 const float* __restrict__ bpos) {
    int idx = blockIdx.x * blockDim.x + threadIdx.x;
    if (idx >= HH * NN) return;
    int h = idx / NN, i = idx - h * NN;
    float W0 = Wpos[h], W1 = Wpos[HH + h], bph = bpos[h];
    float apos = W0 + W1;
    float aneg = W1 - W0;
    float fi = (float)i, fM = (float)(NN - 1 - i);
    float mi = fmaxf(0.f, fmaxf(apos * fi, aneg * fM));

    float Sp;
    if (i == 0)            Sp = 0.f;
    else if (apos > 0.f)   Sp = __expf(apos * fi - mi) * expm1f(-apos * fi) / expm1f(-apos);
    else if (apos < 0.f)   Sp = __expf(apos - mi) * expm1f(apos * fi) / expm1f(apos);
    else                   Sp = fi * __expf(-mi);

    float Sn;
    if (i == NN - 1)       Sn = 0.f;
    else if (aneg > 0.f)   Sn = __expf(aneg * fM - mi) * expm1f(-aneg * fM) / expm1f(-aneg);
    else if (aneg < 0.f)   Sn = __expf(aneg - mi) * expm1f(aneg * fM) / expm1f(aneg);
    else                   Sn = fM * __expf(-mi);

    float den = __expf(-mi) + Sp + Sn;
    g_pm[idx]   = bph + mi;
    g_pinv[idx] = 1.f / den;
}

// ============================================================
// 2) QKV GEMM (f32x2, 128x64 tile) -> bf16 hi/lo q,k,vT + f32 v
// ============================================================
__global__ void __launch_bounds__(256) qkv_gemm_kernel(const float* __restrict__ x,
                                const float* __restrict__ Wqk,
                                const float* __restrict__ Wv) {
    __shared__ float As[16][132];
    __shared__ float Bs[16][68];
    int tid = threadIdx.x;
    int ty = tid >> 4, tx = tid & 15;
    int m0 = blockIdx.x * 128, n0 = blockIdx.y * 64;
    u64 acc[4][4] = {};

    int arow = tid >> 1, akc = (tid & 1) * 8;
    int brow = tid >> 4, bcol = (tid & 15) * 4;

    for (int k0 = 0; k0 < 256; k0 += 16) {
        float4 a0 = *(const float4*)&x[(m0 + arow) * 256 + k0 + akc];
        float4 a1 = *(const float4*)&x[(m0 + arow) * 256 + k0 + akc + 4];
        As[akc + 0][arow] = a0.x; As[akc + 1][arow] = a0.y;
        As[akc + 2][arow] = a0.z; As[akc + 3][arow] = a0.w;
        As[akc + 4][arow] = a1.x; As[akc + 5][arow] = a1.y;
        As[akc + 6][arow] = a1.z; As[akc + 7][arow] = a1.w;
        int gc = n0 + bcol;
        float4 bv;
        if (gc < 512) bv = *(const float4*)&Wqk[(k0 + brow) * 512 + gc];
        else          bv = *(const float4*)&Wv[(k0 + brow) * 256 + gc - 512];
        *(float4*)&Bs[brow][bcol] = bv;
        __syncthreads();
        #pragma unroll
        for (int kk = 0; kk < 16; kk++) {
            ulonglong2 ap0 = *(const ulonglong2*)&As[kk][8 * ty];
            ulonglong2 ap1 = *(const ulonglong2*)&As[kk][8 * ty + 4];
            float4 bv4 = *(const float4*)&Bs[kk][4 * tx];
            u64 b0 = dup2(bv4.x), b1 = dup2(bv4.y), b2 = dup2(bv4.z), b3 = dup2(bv4.w);
            fma2(acc[0][0], ap0.x, b0); fma2(acc[0][1], ap0.x, b1);
            fma2(acc[0][2], ap0.x, b2); fma2(acc[0][3], ap0.x, b3);
            fma2(acc[1][0], ap0.y, b0); fma2(acc[1][1], ap0.y, b1);
            fma2(acc[1][2], ap0.y, b2); fma2(acc[1][3], ap0.y, b3);
            fma2(acc[2][0], ap1.x, b0); fma2(acc[2][1], ap1.x, b1);
            fma2(acc[2][2], ap1.x, b2); fma2(acc[2][3], ap1.x, b3);
            fma2(acc[3][0], ap1.y, b0); fma2(acc[3][1], ap1.y, b1);
            fma2(acc[3][2], ap1.y, b2); fma2(acc[3][3], ap1.y, b3);
        }
        __syncthreads();
    }

    int c0 = n0 + 4 * tx;
    #pragma unroll
    for (int p = 0; p < 4; p++) {
        float vx[4], vy[4];
        #pragma unroll
        for (int j = 0; j < 4; j++) { float2 u = unpack2(acc[p][j]); vx[j] = u.x; vy[j] = u.y; }
        #pragma unroll
        for (int r = 0; r < 2; r++) {
            int m = m0 + 8 * ty + 2 * p + r;
            int b = m >> 11, n = m & (NN - 1);
            float v0 = r ? vy[0] : vx[0];
            float v1 = r ? vy[1] : vx[1];
            float v2 = r ? vy[2] : vx[2];
            float v3 = r ? vy[3] : vx[3];
            if (c0 < 256) {
                int h = c0 >> 5, d0 = c0 & 31;
                int bh = b * HH + h;
                v0 *= SCALE; v1 *= SCALE; v2 *= SCALE; v3 *= SCALE;
                __nv_bfloat16 h0 = __float2bfloat16(v0), h1 = __float2bfloat16(v1);
                __nv_bfloat16 h2 = __float2bfloat16(v2), h3 = __float2bfloat16(v3);
                uint2 hp, lp;
                hp.x = packbf2(__bfloat162float(h0), __bfloat162float(h1));
                hp.y = packbf2(__bfloat162float(h2), __bfloat162float(h3));
                lp.x = packbf2(v0 - __bfloat162float(h0), v1 - __bfloat162float(h1));
                lp.y = packbf2(v2 - __bfloat162float(h2), v3 - __bfloat162float(h3));
                size_t ui = ((size_t)bh * NN + n) * 16 + d0 / 2;
                *(uint2*)((u32*)g_qbh + ui) = hp;
                *(uint2*)((u32*)g_qbl + ui) = lp;
            } else if (c0 < 512) {
                int cc = c0 - 256; int h = cc >> 5, d0 = cc & 31;
                int bh = b * HH + h;
                __nv_bfloat16 h0 = __float2bfloat16(v0), h1 = __float2bfloat16(v1);
                __nv_bfloat16 h2 = __float2bfloat16(v2), h3 = __float2bfloat16(v3);
                uint2 hp, lp;
                hp.x = packbf2(__bfloat162float(h0), __bfloat162float(h1));
                hp.y = packbf2(__bfloat162float(h2), __bfloat162float(h3));
                lp.x = packbf2(v0 - __bfloat162float(h0), v1 - __bfloat162float(h1));
                lp.y = packbf2(v2 - __bfloat162float(h2), v3 - __bfloat162float(h3));
                size_t ui = ((size_t)bh * NN + n) * 16 + d0 / 2;
                *(uint2*)((u32*)g_kbh + ui) = hp;
                *(uint2*)((u32*)g_kbl + ui) = lp;
            } else {
                int cc = c0 - 512; int h = cc >> 5, d0 = cc & 31;
                int bh = b * HH + h;
                *(float4*)&g_v[((size_t)bh * NN + n) * DHH + d0] = make_float4(v0, v1, v2, v3);
                float vv[4] = {v0, v1, v2, v3};
                #pragma unroll
                for (int j = 0; j < 4; j++) {
                    __nv_bfloat16 hb = __float2bfloat16(vv[j]);
                    size_t ti = ((size_t)bh * DHH + d0 + j) * NN + n;
                    g_vth[ti] = hb;
                    g_vtl[ti] = __float2bfloat16(vv[j] - __bfloat162float(hb));
                }
            }
        }
    }
}

// ============================================================
// 3) POS path: blocked-parallel exponential scans, 512 threads
// ============================================================
__global__ void __launch_bounds__(512) pos_scan_kernel(const float* __restrict__ Wpos,
                                                       const float* __restrict__ bpos) {
    __shared__ float TFs[8][32], TGs[8][32], AFs[8][32], DGs[8][32];

    int bh = blockIdx.x;
    int h = bh & (HH - 1);
    int tid = threadIdx.x;
    int w = tid >> 5, lane = tid & 31;
    float apos = Wpos[h] + Wpos[HH + h];
    float aneg = Wpos[HH + h] - Wpos[h];
    bool posg = apos > 0.f, negg = aneg > 0.f;
    float rhoF = posg ? 1.f : __expf(apos);
    float rhoG = negg ? 1.f : __expf(aneg);
    float wcF = posg ? -apos : 0.f;
    float wcG = negg ? -aneg : 0.f;
    float usG = negg ? 1.f : rhoG;

    const float* vp = g_v + (size_t)bh * NN * DHH + lane;
    float* fo = g_scanF + (size_t)bh * NN * DHH + lane;
    float* go = g_scanG + (size_t)bh * NN * DHH + lane;

    if (w < 8) {
        int c0 = w * CH;
        float F = 0.f;
        for (int ib = c0; ib < c0 + CH; ib += 8) {
            float vb[8];
            #pragma unroll
            for (int u = 0; u < 8; u++) vb[u] = vp[(ib + u) * DHH];
            #pragma unroll
            for (int u = 0; u < 8; u++) {
                float uu = vb[u] * __expf(wcF * (float)(ib + u));
                F = rhoF * F + uu;
                fo[(ib + u) * DHH] = F;
            }
        }
        TFs[w][lane] = F;
    } else {
        int c0 = (w - 8) * CH;
        float G = 0.f;
        for (int ib = c0 + CH - 1; ib >= c0; ib -= 8) {
            float vb[8];
            #pragma unroll
            for (int u = 0; u < 8; u++) vb[u] = vp[(ib - u) * DHH];
            #pragma unroll
            for (int u = 0; u < 8; u++) {
                int i = ib - u;
                go[i * DHH] = G;
                float uu = usG * vb[u] * __expf(wcG * (float)(NN - 1 - i));
                G = rhoG * G + uu;
            }
        }
        TGs[w - 8][lane] = G;
    }
    __syncthreads();

    if (w == 0) {
        float fF = posg ? 1.f : __expf(apos * (float)CH);
        float A = 0.f;
        #pragma unroll
        for (int c = 0; c < 8; c++) { AFs[c][lane] = A; A = TFs[c][lane] + fF * A; }
    } else if (w == 8) {
        float fG = negg ? 1.f : __expf(aneg * (float)CH);
        float D = 0.f;
        #pragma unroll
        for (int c = 7; c >= 0; c--) { DGs[c][lane] = D; D = TGs[c][lane] + fG * D; }
    }
    __syncthreads();

    int c = w >> 1;
    int c0 = c * CH;
    int cend = c0 + CH;
    int r0 = w * 128;
    float A = AFs[c][lane];
    float D = DGs[c][lane];
    float pfc = posg ? 0.f : apos;
    float gfc = negg ? 0.f : aneg;
    float bph = bpos[h];
    float pp = fmaxf(apos, 0.f), pn = fmaxf(aneg, 0.f);
    const float* pmrow = g_pm + h * NN;
    for (int ib = r0; ib < r0 + 128; ib += 8) {
        float fb[8], gb[8], pmb[8];
        #pragma unroll
        for (int u = 0; u < 8; u++) {
            fb[u]  = fo[(ib + u) * DHH];
            gb[u]  = go[(ib + u) * DHH];
            pmb[u] = pmrow[ib + u];
        }
        #pragma unroll
        for (int u = 0; u < 8; u++) {
            int i = ib + u;
            float Fg = fb[u] + A * __expf(pfc * (float)(i - c0 + 1));
            float Gg = gb[u] + D * __expf(gfc * (float)(cend - 1 - i));
            float c1 = __expf(bph + pp * (float)i - pmb[u]);
            float c2 = __expf(bph + pn * (float)(NN - 1 - i) - pmb[u]);
            fo[i * DHH] = c1 * Fg + c2 * Gg;
        }
    }
}

// ============================================================
// 4) PATCH attention on mma.sync (HMMA bf16, split hi/lo).
//    Per block: 128 q rows of one (b,h); warp w -> 16 q rows.
//    smem rows padded to 20 b32 (80B) -> conflict-free frag loads.
// ============================================================
__global__ void __launch_bounds__(256, 2) attn_mma_kernel(const float* __restrict__ gating) {
    __shared__ u32 QsH[128 * 20], QsL[128 * 20];
    __shared__ u32 KsH[32 * 20],  KsL[32 * 20];
    __shared__ u32 VsH[32 * 20],  VsL[32 * 20];

    int tid = threadIdx.x;
    int w = tid >> 5, lane = tid & 31, g = lane >> 2, t = lane & 3;
    int qt = blockIdx.x, hidx = blockIdx.y, b = blockIdx.z;
    int bh = b * HH + hidx;
    int q0 = qt * 128;

    const u32* gqh = (const u32*)g_qbh + (size_t)bh * NN * 16;
    const u32* gql = (const u32*)g_qbl + (size_t)bh * NN * 16;
    const u32* gkh = (const u32*)g_kbh + (size_t)bh * NN * 16;
    const u32* gkl = (const u32*)g_kbl + (size_t)bh * NN * 16;
    const u32* gvh = (const u32*)g_vth + (size_t)bh * DHH * (NN / 2);
    const u32* gvl = (const u32*)g_vtl + (size_t)bh * DHH * (NN / 2);

    // stage Q [128][32] hi/lo
    {
        int row = tid >> 1, half = tid & 1;
        const uint4* s0 = (const uint4*)(gqh + (size_t)(q0 + row) * 16 + half * 8);
        uint4 v0 = s0[0], v1 = s0[1];
        uint4* d0 = (uint4*)&QsH[row * 20 + half * 8];
        d0[0] = v0; d0[1] = v1;
        const uint4* s1 = (const uint4*)(gql + (size_t)(q0 + row) * 16 + half * 8);
        v0 = s1[0]; v1 = s1[1];
        uint4* d1 = (uint4*)&QsL[row * 20 + half * 8];
        d1[0] = v0; d1[1] = v1;
    }
    // stage K/V tile 0
    int srow = tid >> 3, spp = tid & 7;
    {
        *(uint2*)&KsH[srow * 20 + spp * 2] = *(const uint2*)(gkh + (size_t)srow * 16 + spp * 2);
        *(uint2*)&KsL[srow * 20 + spp * 2] = *(const uint2*)(gkl + (size_t)srow * 16 + spp * 2);
        *(uint2*)&VsH[srow * 20 + spp * 2] = *(const uint2*)(gvh + (size_t)srow * (NN / 2) + spp * 2);
        *(uint2*)&VsL[srow * 20 + spp * 2] = *(const uint2*)(gvl + (size_t)srow * (NN / 2) + spp * 2);
    }
    __syncthreads();

    // Q fragments: constant across all tiles
    u32 aQh[2][4], aQl[2][4];
    {
        int r0 = 16 * w + g;
        #pragma unroll
        for (int c = 0; c < 2; c++) {
            aQh[c][0] = QsH[r0 * 20 + 8 * c + t];
            aQh[c][1] = QsH[(r0 + 8) * 20 + 8 * c + t];
            aQh[c][2] = QsH[r0 * 20 + 8 * c + t + 4];
            aQh[c][3] = QsH[(r0 + 8) * 20 + 8 * c + t + 4];
            aQl[c][0] = QsL[r0 * 20 + 8 * c + t];
            aQl[c][1] = QsL[(r0 + 8) * 20 + 8 * c + t];
            aQl[c][2] = QsL[r0 * 20 + 8 * c + t + 4];
            aQl[c][3] = QsL[(r0 + 8) * 20 + 8 * c + t + 4];
        }
    }

    float o[4][4] = {};
    float lp0 = 0.f, lp1 = 0.f;

    for (int kt = 0; kt < 64; kt++) {
        // prefetch next tile into registers
        uint2 pkh, pkl, pvh, pvl;
        if (kt < 63) {
            int k0n = (kt + 1) * 32;
            pkh = *(const uint2*)(gkh + (size_t)(k0n + srow) * 16 + spp * 2);
            pkl = *(const uint2*)(gkl + (size_t)(k0n + srow) * 16 + spp * 2);
            pvh = *(const uint2*)(gvh + (size_t)srow * (NN / 2) + k0n / 2 + spp * 2);
            pvl = *(const uint2*)(gvl + (size_t)srow * (NN / 2) + k0n / 2 + spp * 2);
        }
        // ---- QK: S[16q x 32k] via 3-pass split-bf16 mma ----
        float s[4][4] = {};
        #pragma unroll
        for (int j = 0; j < 4; j++) {
            #pragma unroll
            for (int c = 0; c < 2; c++) {
                int base = (8 * j + g) * 20 + 8 * c + t;
                u32 kb0 = KsH[base], kb1 = KsH[base + 4];
                u32 lb0 = KsL[base], lb1 = KsL[base + 4];
                mma_bf16(s[j], aQh[c], kb0, kb1);
                mma_bf16(s[j], aQh[c], lb0, lb1);
                mma_bf16(s[j], aQl[c], kb0, kb1);
            }
        }
        // ---- exp, l, P fragments (register-resident) ----
        float e[4][4];
        #pragma unroll
        for (int j = 0; j < 4; j++) {
            e[j][0] = __expf(s[j][0]); e[j][1] = __expf(s[j][1]);
            e[j][2] = __expf(s[j][2]); e[j][3] = __expf(s[j][3]);
            lp0 += e[j][0] + e[j][1];
            lp1 += e[j][2] + e[j][3];
        }
        u32 pah[2][4], pal[2][4];
        #pragma unroll
        for (int kc = 0; kc < 2; kc++) {
            int j0 = 2 * kc, j1 = 2 * kc + 1;
            float h00 = __bfloat162float(__float2bfloat16(e[j0][0]));
            float h01 = __bfloat162float(__float2bfloat16(e[j0][1]));
            float h02 = __bfloat162float(__float2bfloat16(e[j0][2]));
            float h03 = __bfloat162float(__float2bfloat16(e[j0][3]));
            float h10 = __bfloat162float(__float2bfloat16(e[j1][0]));
            float h11 = __bfloat162float(__float2bfloat16(e[j1][1]));
            float h12 = __bfloat162float(__float2bfloat16(e[j1][2]));
            float h13 = __bfloat162float(__float2bfloat16(e[j1][3]));
            pah[kc][0] = packbf2(h00, h01);
            pah[kc][1] = packbf2(h02, h03);
            pah[kc][2] = packbf2(h10, h11);
            pah[kc][3] = packbf2(h12, h13);
            pal[kc][0] = packbf2(e[j0][0] - h00, e[j0][1] - h01);
            pal[kc][1] = packbf2(e[j0][2] - h02, e[j0][3] - h03);
            pal[kc][2] = packbf2(e[j1][0] - h10, e[j1][1] - h11);
            pal[kc][3] = packbf2(e[j1][2] - h12, e[j1][3] - h13);
        }
        // ---- PV: O[16q x 32d] via 3-pass split-bf16 mma ----
        #pragma unroll
        for (int jj = 0; jj < 4; jj++) {
            #pragma unroll
            for (int kc = 0; kc < 2; kc++) {
                int base = (8 * jj + g) * 20 + 8 * kc + t;
                u32 vb0 = VsH[base], vb1 = VsH[base + 4];
                u32 wb0 = VsL[base], wb1 = VsL[base + 4];
                mma_bf16(o[jj], pah[kc], vb0, vb1);
                mma_bf16(o[jj], pal[kc], vb0, vb1);
                mma_bf16(o[jj], pah[kc], wb0, wb1);
            }
        }
        __syncthreads();   // all warps done reading K/V smem
        if (kt < 63) {
            *(uint2*)&KsH[srow * 20 + spp * 2] = pkh;
            *(uint2*)&KsL[srow * 20 + spp * 2] = pkl;
            *(uint2*)&VsH[srow * 20 + spp * 2] = pvh;
            *(uint2*)&VsL[srow * 20 + spp * 2] = pvl;
        }
        __syncthreads();   // next tile staged
    }

    // ---- epilogue ----
    lp0 += __shfl_xor_sync(0xffffffffu, lp0, 1);
    lp0 += __shfl_xor_sync(0xffffffffu, lp0, 2);
    lp1 += __shfl_xor_sync(0xffffffffu, lp1, 1);
    lp1 += __shfl_xor_sync(0xffffffffu, lp1, 2);

    float gv = 1.f / (1.f + __expf(-gating[hidx]));
    int row0 = q0 + 16 * w + g, row1 = row0 + 8;
    float s1a = (1.f - gv) / lp0, s1b = (1.f - gv) / lp1;
    float s2a = gv * g_pinv[hidx * NN + row0];
    float s2b = gv * g_pinv[hidx * NN + row1];

    #pragma unroll
    for (int jj = 0; jj < 4; jj++) {
        int dh = 8 * jj + 2 * t;
        float2 p0 = *(const float2*)&g_scanF[((size_t)bh * NN + row0) * DHH + dh];
        float2 p1 = *(const float2*)&g_scanF[((size_t)bh * NN + row1) * DHH + dh];
        float2 o0 = make_float2(s1a * o[jj][0] + s2a * p0.x, s1a * o[jj][1] + s2a * p0.y);
        float2 o1 = make_float2(s1b * o[jj][2] + s2b * p1.x, s1b * o[jj][3] + s2b * p1.y);
        int col = hidx * 32 + dh;
        *(float2*)&g_ctx[((size_t)b * NN + row0) * CC + col] = o0;
        *(float2*)&g_ctx[((size_t)b * NN + row1) * CC + col] = o1;
    }
}

// ============================================================
// 5) Output projection, f32x2 register-dup, 128x64 tile
// ============================================================
__global__ void __launch_bounds__(256) proj_gemm_kernel(const float* __restrict__ Wp,
                                 const float* __restrict__ bp,
                                 float* __restrict__ out) {
    __shared__ float As[16][132];
    __shared__ float Bs[16][68];
    int tid = threadIdx.x;
    int ty = tid >> 4, tx = tid & 15;
    int m0 = blockIdx.x * 128, n0 = blockIdx.y * 64;
    u64 acc[4][4] = {};

    int arow = tid >> 1, akc = (tid & 1) * 8;
    int brow = tid >> 4, bcol = (tid & 15) * 4;

    for (int k0 = 0; k0 < 256; k0 += 16) {
        float4 a0 = *(const float4*)&g_ctx[(m0 + arow) * 256 + k0 + akc];
        float4 a1 = *(const float4*)&g_ctx[(m0 + arow) * 256 + k0 + akc + 4];
        As[akc + 0][arow] = a0.x; As[akc + 1][arow] = a0.y;
        As[akc + 2][arow] = a0.z; As[akc + 3][arow] = a0.w;
        As[akc + 4][arow] = a1.x; As[akc + 5][arow] = a1.y;
        As[akc + 6][arow] = a1.z; As[akc + 7][arow] = a1.w;
        *(float4*)&Bs[brow][bcol] = *(const float4*)&Wp[(k0 + brow) * 256 + n0 + bcol];
        __syncthreads();
        #pragma unroll
        for (int kk = 0; kk < 16; kk++) {
            ulonglong2 ap0 = *(const ulonglong2*)&As[kk][8 * ty];
            ulonglong2 ap1 = *(const ulonglong2*)&As[kk][8 * ty + 4];
            float4 bv4 = *(const float4*)&Bs[kk][4 * tx];
            u64 b0 = dup2(bv4.x), b1 = dup2(bv4.y), b2 = dup2(bv4.z), b3 = dup2(bv4.w);
            fma2(acc[0][0], ap0.x, b0); fma2(acc[0][1], ap0.x, b1);
            fma2(acc[0][2], ap0.x, b2); fma2(acc[0][3], ap0.x, b3);
            fma2(acc[1][0], ap0.y, b0); fma2(acc[1][1], ap0.y, b1);
            fma2(acc[1][2], ap0.y, b2); fma2(acc[1][3], ap0.y, b3);
            fma2(acc[2][0], ap1.x, b0); fma2(acc[2][1], ap1.x, b1);
            fma2(acc[2][2], ap1.x, b2); fma2(acc[2][3], ap1.x, b3);
            fma2(acc[3][0], ap1.y, b0); fma2(acc[3][1], ap1.y, b1);
            fma2(acc[3][2], ap1.y, b2); fma2(acc[3][3], ap1.y, b3);
        }
        __syncthreads();
    }
    #pragma unroll
    for (int p = 0; p < 4; p++) {
        #pragma unroll
        for (int j = 0; j < 4; j++) {
            float2 v2 = unpack2(acc[p][j]);
            int c = n0 + 4 * tx + j;
            int m = m0 + 8 * ty + 2 * p;
            out[m * 256 + c]       = v2.x + bp[c];
            out[(m + 1) * 256 + c] = v2.y + bp[c];
        }
    }
}

// ============================================================
extern "C" void kernel_launch(void* const* d_in, const int* in_sizes, int n_in,
                              void* d_out, int out_size) {
    const float* x     = (const float*)d_in[0];
    const float* Wqk   = (const float*)d_in[1];
    const float* Wv    = (const float*)d_in[2];
    const float* Wproj = (const float*)d_in[3];
    const float* bproj = (const float*)d_in[4];
    const float* Wpos  = (const float*)d_in[5];
    const float* bpos  = (const float*)d_in[6];
    const float* gate  = (const float*)d_in[7];
    float* out = (float*)d_out;

    pos_stats_kernel<<<(HH * NN + 255) / 256, 256>>>(Wpos, bpos);
    qkv_gemm_kernel<<<dim3(BB * NN / 128, 12), 256>>>(x, Wqk, Wv);
    pos_scan_kernel<<<BB * HH, 512>>>(Wpos, bpos);
    attn_mma_kernel<<<dim3(NN / 128, HH, BB), 256>>>(gate);
    proj_gemm_kernel<<<dim3(BB * NN / 128, 4), 256>>>(Wproj, bproj, out);
}

// round 13
// speedup vs baseline: 2.9888x; 1.2258x over previous
#include <cuda_runtime.h>
#include <cuda_bf16.h>
#include <math.h>

#define BB 2
#define NN 2048
#define CC 256
#define HH 8
#define DHH 32
#define SCALE 0.17677669529663687f  // 1/sqrt(32)
#define CH 256                       // scan chunk size (NN/8)

typedef unsigned long long u64;
typedef unsigned u32;

// ---- scratch ----
__device__ __nv_bfloat16 g_qbh[BB*HH*NN*DHH];  // [bh][n][d] hi, pre-scaled
__device__ __nv_bfloat16 g_qbl[BB*HH*NN*DHH];  // lo
__device__ __nv_bfloat16 g_kbh[BB*HH*NN*DHH];  // [bh][n][d] hi
__device__ __nv_bfloat16 g_kbl[BB*HH*NN*DHH];
__device__ __nv_bfloat16 g_vth[BB*HH*DHH*NN];  // [bh][d][n] hi (transposed)
__device__ __nv_bfloat16 g_vtl[BB*HH*DHH*NN];
__device__ float g_v [BB*HH*NN*DHH];           // [bh][n][d] f32 (scan input)
__device__ float g_ctx[BB*NN*CC];
__device__ float g_pm[HH*NN];
__device__ float g_pinv[HH*NN];
__device__ float g_scanF[BB*HH*NN*DHH];
__device__ float g_scanG[BB*HH*NN*DHH];

// ---- mma.sync bf16 (sm_80+ PTX; valid at compute_103) ----
__device__ __forceinline__ void mma_bf16(float d[4], const u32 a[4], u32 b0, u32 b1) {
    asm volatile(
        "mma.sync.aligned.m16n8k16.row.col.f32.bf16.bf16.f32 "
        "{%0,%1,%2,%3}, {%4,%5,%6,%7}, {%8,%9}, {%0,%1,%2,%3};"
        : "+f"(d[0]), "+f"(d[1]), "+f"(d[2]), "+f"(d[3])
        : "r"(a[0]), "r"(a[1]), "r"(a[2]), "r"(a[3]), "r"(b0), "r"(b1));
}
__device__ __forceinline__ u32 packbf2(float lo, float hi) {
    __nv_bfloat162 v = __floats2bfloat162_rn(lo, hi);
    return *(u32*)&v;
}
__device__ __forceinline__ void split2(float v0, float v1, u32 &hp, u32 &lp) {
    float h0 = __bfloat162float(__float2bfloat16(v0));
    float h1 = __bfloat162float(__float2bfloat16(v1));
    hp = packbf2(h0, h1);
    lp = packbf2(v0 - h0, v1 - h1);
}

// ============================================================
// 1) pos softmax row stats, closed form (geometric series)
// ============================================================
__global__ void pos_stats_kernel(const float* __restrict__ Wpos,
                                 const float* __restrict__ bpos) {
    int idx = blockIdx.x * blockDim.x + threadIdx.x;
    if (idx >= HH * NN) return;
    int h = idx / NN, i = idx - h * NN;
    float W0 = Wpos[h], W1 = Wpos[HH + h], bph = bpos[h];
    float apos = W0 + W1;
    float aneg = W1 - W0;
    float fi = (float)i, fM = (float)(NN - 1 - i);
    float mi = fmaxf(0.f, fmaxf(apos * fi, aneg * fM));

    float Sp;
    if (i == 0)            Sp = 0.f;
    else if (apos > 0.f)   Sp = __expf(apos * fi - mi) * expm1f(-apos * fi) / expm1f(-apos);
    else if (apos < 0.f)   Sp = __expf(apos - mi) * expm1f(apos * fi) / expm1f(apos);
    else                   Sp = fi * __expf(-mi);

    float Sn;
    if (i == NN - 1)       Sn = 0.f;
    else if (aneg > 0.f)   Sn = __expf(aneg * fM - mi) * expm1f(-aneg * fM) / expm1f(-aneg);
    else if (aneg < 0.f)   Sn = __expf(aneg - mi) * expm1f(aneg * fM) / expm1f(aneg);
    else                   Sn = fM * __expf(-mi);

    float den = __expf(-mi) + Sp + Sn;
    g_pm[idx]   = bph + mi;
    g_pinv[idx] = 1.f / den;
}

// ============================================================
// 2) QKV GEMM on mma.sync split-bf16 (3-pass).
//    128m x 64n tile, K chunks of 32. grid (32, 12).
//    Epilogue scatters bf16 hi/lo q,k,vT + f32 v.
// ============================================================
__global__ void __launch_bounds__(256) qkv_tc_kernel(const float* __restrict__ x,
                                                     const float* __restrict__ Wqk,
                                                     const float* __restrict__ Wv) {
    __shared__ u32 sAh[128 * 20], sAl[128 * 20];
    __shared__ u32 sBh[64 * 20],  sBl[64 * 20];

    int tid = threadIdx.x;
    int w = tid >> 5, lane = tid & 31, g = lane >> 2, t = lane & 3;
    int m0 = blockIdx.x * 128, n0 = blockIdx.y * 64;

    const float* Wsrc; int ldw, coff;
    if (n0 < 512) { Wsrc = Wqk; ldw = 512; coff = n0; }
    else          { Wsrc = Wv;  ldw = 256; coff = n0 - 512; }

    int arow = tid >> 1, ahalf = tid & 1;
    int bn = tid & 63, bkg = tid >> 6;

    float o[8][4] = {};

    for (int kc = 0; kc < 8; kc++) {
        int k0 = kc * 32;
        __syncthreads();
        // ---- stage A: x[128][32] split hi/lo ----
        {
            const float* xs = &x[(size_t)(m0 + arow) * 256 + k0 + ahalf * 16];
            float4 f0 = *(const float4*)xs, f1 = *(const float4*)(xs + 4);
            float4 f2 = *(const float4*)(xs + 8), f3 = *(const float4*)(xs + 12);
            u32 hi[8], lo[8];
            split2(f0.x, f0.y, hi[0], lo[0]); split2(f0.z, f0.w, hi[1], lo[1]);
            split2(f1.x, f1.y, hi[2], lo[2]); split2(f1.z, f1.w, hi[3], lo[3]);
            split2(f2.x, f2.y, hi[4], lo[4]); split2(f2.z, f2.w, hi[5], lo[5]);
            split2(f3.x, f3.y, hi[6], lo[6]); split2(f3.z, f3.w, hi[7], lo[7]);
            uint4* dh = (uint4*)&sAh[arow * 20 + ahalf * 8];
            dh[0] = make_uint4(hi[0], hi[1], hi[2], hi[3]);
            dh[1] = make_uint4(hi[4], hi[5], hi[6], hi[7]);
            uint4* dl = (uint4*)&sAl[arow * 20 + ahalf * 8];
            dl[0] = make_uint4(lo[0], lo[1], lo[2], lo[3]);
            dl[1] = make_uint4(lo[4], lo[5], lo[6], lo[7]);
        }
        // ---- stage B: W^T[64n][32k] split hi/lo ----
        {
            float wv[8];
            #pragma unroll
            for (int i = 0; i < 8; i++)
                wv[i] = Wsrc[(size_t)(k0 + bkg * 8 + i) * ldw + coff + bn];
            u32 bh4[4], bl4[4];
            split2(wv[0], wv[1], bh4[0], bl4[0]);
            split2(wv[2], wv[3], bh4[1], bl4[1]);
            split2(wv[4], wv[5], bh4[2], bl4[2]);
            split2(wv[6], wv[7], bh4[3], bl4[3]);
            *(uint4*)&sBh[bn * 20 + bkg * 4] = make_uint4(bh4[0], bh4[1], bh4[2], bh4[3]);
            *(uint4*)&sBl[bn * 20 + bkg * 4] = make_uint4(bl4[0], bl4[1], bl4[2], bl4[3]);
        }
        __syncthreads();

        // ---- fragments + mma ----
        u32 aH[2][4], aL[2][4];
        int r0 = 16 * w + g;
        #pragma unroll
        for (int c = 0; c < 2; c++) {
            aH[c][0] = sAh[r0 * 20 + 8 * c + t];
            aH[c][1] = sAh[(r0 + 8) * 20 + 8 * c + t];
            aH[c][2] = sAh[r0 * 20 + 8 * c + t + 4];
            aH[c][3] = sAh[(r0 + 8) * 20 + 8 * c + t + 4];
            aL[c][0] = sAl[r0 * 20 + 8 * c + t];
            aL[c][1] = sAl[(r0 + 8) * 20 + 8 * c + t];
            aL[c][2] = sAl[r0 * 20 + 8 * c + t + 4];
            aL[c][3] = sAl[(r0 + 8) * 20 + 8 * c + t + 4];
        }
        #pragma unroll
        for (int j = 0; j < 8; j++) {
            #pragma unroll
            for (int c = 0; c < 2; c++) {
                int base = (8 * j + g) * 20 + 8 * c + t;
                u32 b0 = sBh[base], b1 = sBh[base + 4];
                u32 c0 = sBl[base], c1 = sBl[base + 4];
                mma_bf16(o[j], aH[c], b0, b1);
                mma_bf16(o[j], aH[c], c0, c1);
                mma_bf16(o[j], aL[c], b0, b1);
            }
        }
    }

    // ---- epilogue: scatter to q/k/v layouts ----
    int row_a = m0 + 16 * w + g;
    #pragma unroll
    for (int j = 0; j < 8; j++) {
        int c = n0 + 8 * j + 2 * t;
        #pragma unroll
        for (int r = 0; r < 2; r++) {
            int m = row_a + 8 * r;
            float v0 = o[j][2 * r], v1 = o[j][2 * r + 1];
            int b = m >> 11, n = m & (NN - 1);
            if (c < 256) {
                int h = c >> 5, d0 = c & 31;
                int bh = b * HH + h;
                v0 *= SCALE; v1 *= SCALE;
                u32 hp, lp;
                split2(v0, v1, hp, lp);
                size_t ui = ((size_t)bh * NN + n) * 16 + (d0 >> 1);
                ((u32*)g_qbh)[ui] = hp;
                ((u32*)g_qbl)[ui] = lp;
            } else if (c < 512) {
                int cc = c - 256; int h = cc >> 5, d0 = cc & 31;
                int bh = b * HH + h;
                u32 hp, lp;
                split2(v0, v1, hp, lp);
                size_t ui = ((size_t)bh * NN + n) * 16 + (d0 >> 1);
                ((u32*)g_kbh)[ui] = hp;
                ((u32*)g_kbl)[ui] = lp;
            } else {
                int cc = c - 512; int h = cc >> 5, d0 = cc & 31;
                int bh = b * HH + h;
                *(float2*)&g_v[((size_t)bh * NN + n) * DHH + d0] = make_float2(v0, v1);
                __nv_bfloat16 h0 = __float2bfloat16(v0);
                __nv_bfloat16 h1 = __float2bfloat16(v1);
                size_t t0 = ((size_t)bh * DHH + d0) * NN + n;
                g_vth[t0]      = h0;
                g_vtl[t0]      = __float2bfloat16(v0 - __bfloat162float(h0));
                g_vth[t0 + NN] = h1;
                g_vtl[t0 + NN] = __float2bfloat16(v1 - __bfloat162float(h1));
            }
        }
    }
}

// ============================================================
// 3) POS path: blocked-parallel exponential scans, 512 threads
// ============================================================
__global__ void __launch_bounds__(512) pos_scan_kernel(const float* __restrict__ Wpos,
                                                       const float* __restrict__ bpos) {
    __shared__ float TFs[8][32], TGs[8][32], AFs[8][32], DGs[8][32];

    int bh = blockIdx.x;
    int h = bh & (HH - 1);
    int tid = threadIdx.x;
    int w = tid >> 5, lane = tid & 31;
    float apos = Wpos[h] + Wpos[HH + h];
    float aneg = Wpos[HH + h] - Wpos[h];
    bool posg = apos > 0.f, negg = aneg > 0.f;
    float rhoF = posg ? 1.f : __expf(apos);
    float rhoG = negg ? 1.f : __expf(aneg);
    float wcF = posg ? -apos : 0.f;
    float wcG = negg ? -aneg : 0.f;
    float usG = negg ? 1.f : rhoG;

    const float* vp = g_v + (size_t)bh * NN * DHH + lane;
    float* fo = g_scanF + (size_t)bh * NN * DHH + lane;
    float* go = g_scanG + (size_t)bh * NN * DHH + lane;

    if (w < 8) {
        int c0 = w * CH;
        float F = 0.f;
        for (int ib = c0; ib < c0 + CH; ib += 8) {
            float vb[8];
            #pragma unroll
            for (int u = 0; u < 8; u++) vb[u] = vp[(ib + u) * DHH];
            #pragma unroll
            for (int u = 0; u < 8; u++) {
                float uu = vb[u] * __expf(wcF * (float)(ib + u));
                F = rhoF * F + uu;
                fo[(ib + u) * DHH] = F;
            }
        }
        TFs[w][lane] = F;
    } else {
        int c0 = (w - 8) * CH;
        float G = 0.f;
        for (int ib = c0 + CH - 1; ib >= c0; ib -= 8) {
            float vb[8];
            #pragma unroll
            for (int u = 0; u < 8; u++) vb[u] = vp[(ib - u) * DHH];
            #pragma unroll
            for (int u = 0; u < 8; u++) {
                int i = ib - u;
                go[i * DHH] = G;
                float uu = usG * vb[u] * __expf(wcG * (float)(NN - 1 - i));
                G = rhoG * G + uu;
            }
        }
        TGs[w - 8][lane] = G;
    }
    __syncthreads();

    if (w == 0) {
        float fF = posg ? 1.f : __expf(apos * (float)CH);
        float A = 0.f;
        #pragma unroll
        for (int c = 0; c < 8; c++) { AFs[c][lane] = A; A = TFs[c][lane] + fF * A; }
    } else if (w == 8) {
        float fG = negg ? 1.f : __expf(aneg * (float)CH);
        float D = 0.f;
        #pragma unroll
        for (int c = 7; c >= 0; c--) { DGs[c][lane] = D; D = TGs[c][lane] + fG * D; }
    }
    __syncthreads();

    int c = w >> 1;
    int c0 = c * CH;
    int cend = c0 + CH;
    int r0 = w * 128;
    float A = AFs[c][lane];
    float D = DGs[c][lane];
    float pfc = posg ? 0.f : apos;
    float gfc = negg ? 0.f : aneg;
    float bph = bpos[h];
    float pp = fmaxf(apos, 0.f), pn = fmaxf(aneg, 0.f);
    const float* pmrow = g_pm + h * NN;
    for (int ib = r0; ib < r0 + 128; ib += 8) {
        float fb[8], gb[8], pmb[8];
        #pragma unroll
        for (int u = 0; u < 8; u++) {
            fb[u]  = fo[(ib + u) * DHH];
            gb[u]  = go[(ib + u) * DHH];
            pmb[u] = pmrow[ib + u];
        }
        #pragma unroll
        for (int u = 0; u < 8; u++) {
            int i = ib + u;
            float Fg = fb[u] + A * __expf(pfc * (float)(i - c0 + 1));
            float Gg = gb[u] + D * __expf(gfc * (float)(cend - 1 - i));
            float c1 = __expf(bph + pp * (float)i - pmb[u]);
            float c2 = __expf(bph + pn * (float)(NN - 1 - i) - pmb[u]);
            fo[i * DHH] = c1 * Fg + c2 * Gg;
        }
    }
}

// ============================================================
// 4) PATCH attention on mma.sync (unchanged from round 12)
// ============================================================
__global__ void __launch_bounds__(256, 2) attn_mma_kernel(const float* __restrict__ gating) {
    __shared__ u32 QsH[128 * 20], QsL[128 * 20];
    __shared__ u32 KsH[32 * 20],  KsL[32 * 20];
    __shared__ u32 VsH[32 * 20],  VsL[32 * 20];

    int tid = threadIdx.x;
    int w = tid >> 5, lane = tid & 31, g = lane >> 2, t = lane & 3;
    int qt = blockIdx.x, hidx = blockIdx.y, b = blockIdx.z;
    int bh = b * HH + hidx;
    int q0 = qt * 128;

    const u32* gqh = (const u32*)g_qbh + (size_t)bh * NN * 16;
    const u32* gql = (const u32*)g_qbl + (size_t)bh * NN * 16;
    const u32* gkh = (const u32*)g_kbh + (size_t)bh * NN * 16;
    const u32* gkl = (const u32*)g_kbl + (size_t)bh * NN * 16;
    const u32* gvh = (const u32*)g_vth + (size_t)bh * DHH * (NN / 2);
    const u32* gvl = (const u32*)g_vtl + (size_t)bh * DHH * (NN / 2);

    {
        int row = tid >> 1, half = tid & 1;
        const uint4* s0 = (const uint4*)(gqh + (size_t)(q0 + row) * 16 + half * 8);
        uint4 v0 = s0[0], v1 = s0[1];
        uint4* d0 = (uint4*)&QsH[row * 20 + half * 8];
        d0[0] = v0; d0[1] = v1;
        const uint4* s1 = (const uint4*)(gql + (size_t)(q0 + row) * 16 + half * 8);
        v0 = s1[0]; v1 = s1[1];
        uint4* d1 = (uint4*)&QsL[row * 20 + half * 8];
        d1[0] = v0; d1[1] = v1;
    }
    int srow = tid >> 3, spp = tid & 7;
    {
        *(uint2*)&KsH[srow * 20 + spp * 2] = *(const uint2*)(gkh + (size_t)srow * 16 + spp * 2);
        *(uint2*)&KsL[srow * 20 + spp * 2] = *(const uint2*)(gkl + (size_t)srow * 16 + spp * 2);
        *(uint2*)&VsH[srow * 20 + spp * 2] = *(const uint2*)(gvh + (size_t)srow * (NN / 2) + spp * 2);
        *(uint2*)&VsL[srow * 20 + spp * 2] = *(const uint2*)(gvl + (size_t)srow * (NN / 2) + spp * 2);
    }
    __syncthreads();

    u32 aQh[2][4], aQl[2][4];
    {
        int r0 = 16 * w + g;
        #pragma unroll
        for (int c = 0; c < 2; c++) {
            aQh[c][0] = QsH[r0 * 20 + 8 * c + t];
            aQh[c][1] = QsH[(r0 + 8) * 20 + 8 * c + t];
            aQh[c][2] = QsH[r0 * 20 + 8 * c + t + 4];
            aQh[c][3] = QsH[(r0 + 8) * 20 + 8 * c + t + 4];
            aQl[c][0] = QsL[r0 * 20 + 8 * c + t];
            aQl[c][1] = QsL[(r0 + 8) * 20 + 8 * c + t];
            aQl[c][2] = QsL[r0 * 20 + 8 * c + t + 4];
            aQl[c][3] = QsL[(r0 + 8) * 20 + 8 * c + t + 4];
        }
    }

    float o[4][4] = {};
    float lp0 = 0.f, lp1 = 0.f;

    for (int kt = 0; kt < 64; kt++) {
        uint2 pkh, pkl, pvh, pvl;
        if (kt < 63) {
            int k0n = (kt + 1) * 32;
            pkh = *(const uint2*)(gkh + (size_t)(k0n + srow) * 16 + spp * 2);
            pkl = *(const uint2*)(gkl + (size_t)(k0n + srow) * 16 + spp * 2);
            pvh = *(const uint2*)(gvh + (size_t)srow * (NN / 2) + k0n / 2 + spp * 2);
            pvl = *(const uint2*)(gvl + (size_t)srow * (NN / 2) + k0n / 2 + spp * 2);
        }
        float s[4][4] = {};
        #pragma unroll
        for (int j = 0; j < 4; j++) {
            #pragma unroll
            for (int c = 0; c < 2; c++) {
                int base = (8 * j + g) * 20 + 8 * c + t;
                u32 kb0 = KsH[base], kb1 = KsH[base + 4];
                u32 lb0 = KsL[base], lb1 = KsL[base + 4];
                mma_bf16(s[j], aQh[c], kb0, kb1);
                mma_bf16(s[j], aQh[c], lb0, lb1);
                mma_bf16(s[j], aQl[c], kb0, kb1);
            }
        }
        float e[4][4];
        #pragma unroll
        for (int j = 0; j < 4; j++) {
            e[j][0] = __expf(s[j][0]); e[j][1] = __expf(s[j][1]);
            e[j][2] = __expf(s[j][2]); e[j][3] = __expf(s[j][3]);
            lp0 += e[j][0] + e[j][1];
            lp1 += e[j][2] + e[j][3];
        }
        u32 pah[2][4], pal[2][4];
        #pragma unroll
        for (int kc = 0; kc < 2; kc++) {
            int j0 = 2 * kc, j1 = 2 * kc + 1;
            float h00 = __bfloat162float(__float2bfloat16(e[j0][0]));
            float h01 = __bfloat162float(__float2bfloat16(e[j0][1]));
            float h02 = __bfloat162float(__float2bfloat16(e[j0][2]));
            float h03 = __bfloat162float(__float2bfloat16(e[j0][3]));
            float h10 = __bfloat162float(__float2bfloat16(e[j1][0]));
            float h11 = __bfloat162float(__float2bfloat16(e[j1][1]));
            float h12 = __bfloat162float(__float2bfloat16(e[j1][2]));
            float h13 = __bfloat162float(__float2bfloat16(e[j1][3]));
            pah[kc][0] = packbf2(h00, h01);
            pah[kc][1] = packbf2(h02, h03);
            pah[kc][2] = packbf2(h10, h11);
            pah[kc][3] = packbf2(h12, h13);
            pal[kc][0] = packbf2(e[j0][0] - h00, e[j0][1] - h01);
            pal[kc][1] = packbf2(e[j0][2] - h02, e[j0][3] - h03);
            pal[kc][2] = packbf2(e[j1][0] - h10, e[j1][1] - h11);
            pal[kc][3] = packbf2(e[j1][2] - h12, e[j1][3] - h13);
        }
        #pragma unroll
        for (int jj = 0; jj < 4; jj++) {
            #pragma unroll
            for (int kc = 0; kc < 2; kc++) {
                int base = (8 * jj + g) * 20 + 8 * kc + t;
                u32 vb0 = VsH[base], vb1 = VsH[base + 4];
                u32 wb0 = VsL[base], wb1 = VsL[base + 4];
                mma_bf16(o[jj], pah[kc], vb0, vb1);
                mma_bf16(o[jj], pal[kc], vb0, vb1);
                mma_bf16(o[jj], pah[kc], wb0, wb1);
            }
        }
        __syncthreads();
        if (kt < 63) {
            *(uint2*)&KsH[srow * 20 + spp * 2] = pkh;
            *(uint2*)&KsL[srow * 20 + spp * 2] = pkl;
            *(uint2*)&VsH[srow * 20 + spp * 2] = pvh;
            *(uint2*)&VsL[srow * 20 + spp * 2] = pvl;
        }
        __syncthreads();
    }

    lp0 += __shfl_xor_sync(0xffffffffu, lp0, 1);
    lp0 += __shfl_xor_sync(0xffffffffu, lp0, 2);
    lp1 += __shfl_xor_sync(0xffffffffu, lp1, 1);
    lp1 += __shfl_xor_sync(0xffffffffu, lp1, 2);

    float gv = 1.f / (1.f + __expf(-gating[hidx]));
    int row0 = q0 + 16 * w + g, row1 = row0 + 8;
    float s1a = (1.f - gv) / lp0, s1b = (1.f - gv) / lp1;
    float s2a = gv * g_pinv[hidx * NN + row0];
    float s2b = gv * g_pinv[hidx * NN + row1];

    #pragma unroll
    for (int jj = 0; jj < 4; jj++) {
        int dh = 8 * jj + 2 * t;
        float2 p0 = *(const float2*)&g_scanF[((size_t)bh * NN + row0) * DHH + dh];
        float2 p1 = *(const float2*)&g_scanF[((size_t)bh * NN + row1) * DHH + dh];
        float2 o0 = make_float2(s1a * o[jj][0] + s2a * p0.x, s1a * o[jj][1] + s2a * p0.y);
        float2 o1 = make_float2(s1b * o[jj][2] + s2b * p1.x, s1b * o[jj][3] + s2b * p1.y);
        int col = hidx * 32 + dh;
        *(float2*)&g_ctx[((size_t)b * NN + row0) * CC + col] = o0;
        *(float2*)&g_ctx[((size_t)b * NN + row1) * CC + col] = o1;
    }
}

// ============================================================
// 5) Output projection on mma.sync split-bf16 (3-pass).
//    128m x 64n tile. grid (32, 4).
// ============================================================
__global__ void __launch_bounds__(256) proj_tc_kernel(const float* __restrict__ Wp,
                                                      const float* __restrict__ bp,
                                                      float* __restrict__ out) {
    __shared__ u32 sAh[128 * 20], sAl[128 * 20];
    __shared__ u32 sBh[64 * 20],  sBl[64 * 20];

    int tid = threadIdx.x;
    int w = tid >> 5, lane = tid & 31, g = lane >> 2, t = lane & 3;
    int m0 = blockIdx.x * 128, n0 = blockIdx.y * 64;

    int arow = tid >> 1, ahalf = tid & 1;
    int bn = tid & 63, bkg = tid >> 6;

    float o[8][4] = {};

    for (int kc = 0; kc < 8; kc++) {
        int k0 = kc * 32;
        __syncthreads();
        {
            const float* xs = &g_ctx[(size_t)(m0 + arow) * 256 + k0 + ahalf * 16];
            float4 f0 = *(const float4*)xs, f1 = *(const float4*)(xs + 4);
            float4 f2 = *(const float4*)(xs + 8), f3 = *(const float4*)(xs + 12);
            u32 hi[8], lo[8];
            split2(f0.x, f0.y, hi[0], lo[0]); split2(f0.z, f0.w, hi[1], lo[1]);
            split2(f1.x, f1.y, hi[2], lo[2]); split2(f1.z, f1.w, hi[3], lo[3]);
            split2(f2.x, f2.y, hi[4], lo[4]); split2(f2.z, f2.w, hi[5], lo[5]);
            split2(f3.x, f3.y, hi[6], lo[6]); split2(f3.z, f3.w, hi[7], lo[7]);
            uint4* dh = (uint4*)&sAh[arow * 20 + ahalf * 8];
            dh[0] = make_uint4(hi[0], hi[1], hi[2], hi[3]);
            dh[1] = make_uint4(hi[4], hi[5], hi[6], hi[7]);
            uint4* dl = (uint4*)&sAl[arow * 20 + ahalf * 8];
            dl[0] = make_uint4(lo[0], lo[1], lo[2], lo[3]);
            dl[1] = make_uint4(lo[4], lo[5], lo[6], lo[7]);
        }
        {
            float wv[8];
            #pragma unroll
            for (int i = 0; i < 8; i++)
                wv[i] = Wp[(size_t)(k0 + bkg * 8 + i) * 256 + n0 + bn];
            u32 bh4[4], bl4[4];
            split2(wv[0], wv[1], bh4[0], bl4[0]);
            split2(wv[2], wv[3], bh4[1], bl4[1]);
            split2(wv[4], wv[5], bh4[2], bl4[2]);
            split2(wv[6], wv[7], bh4[3], bl4[3]);
            *(uint4*)&sBh[bn * 20 + bkg * 4] = make_uint4(bh4[0], bh4[1], bh4[2], bh4[3]);
            *(uint4*)&sBl[bn * 20 + bkg * 4] = make_uint4(bl4[0], bl4[1], bl4[2], bl4[3]);
        }
        __syncthreads();

        u32 aH[2][4], aL[2][4];
        int r0 = 16 * w + g;
        #pragma unroll
        for (int c = 0; c < 2; c++) {
            aH[c][0] = sAh[r0 * 20 + 8 * c + t];
            aH[c][1] = sAh[(r0 + 8) * 20 + 8 * c + t];
            aH[c][2] = sAh[r0 * 20 + 8 * c + t + 4];
            aH[c][3] = sAh[(r0 + 8) * 20 + 8 * c + t + 4];
            aL[c][0] = sAl[r0 * 20 + 8 * c + t];
            aL[c][1] = sAl[(r0 + 8) * 20 + 8 * c + t];
            aL[c][2] = sAl[r0 * 20 + 8 * c + t + 4];
            aL[c][3] = sAl[(r0 + 8) * 20 + 8 * c + t + 4];
        }
        #pragma unroll
        for (int j = 0; j < 8; j++) {
            #pragma unroll
            for (int c = 0; c < 2; c++) {
                int base = (8 * j + g) * 20 + 8 * c + t;
                u32 b0 = sBh[base], b1 = sBh[base + 4];
                u32 c0 = sBl[base], c1 = sBl[base + 4];
                mma_bf16(o[j], aH[c], b0, b1);
                mma_bf16(o[j], aH[c], c0, c1);
                mma_bf16(o[j], aL[c], b0, b1);
            }
        }
    }

    int row_a = m0 + 16 * w + g;
    #pragma unroll
    for (int j = 0; j < 8; j++) {
        int c = n0 + 8 * j + 2 * t;
        float2 bpc = *(const float2*)&bp[c];
        #pragma unroll
        for (int r = 0; r < 2; r++) {
            int m = row_a + 8 * r;
            *(float2*)&out[(size_t)m * 256 + c] =
                make_float2(o[j][2 * r] + bpc.x, o[j][2 * r + 1] + bpc.y);
        }
    }
}

// ============================================================
extern "C" void kernel_launch(void* const* d_in, const int* in_sizes, int n_in,
                              void* d_out, int out_size) {
    const float* x     = (const float*)d_in[0];
    const float* Wqk   = (const float*)d_in[1];
    const float* Wv    = (const float*)d_in[2];
    const float* Wproj = (const float*)d_in[3];
    const float* bproj = (const float*)d_in[4];
    const float* Wpos  = (const float*)d_in[5];
    const float* bpos  = (const float*)d_in[6];
    const float* gate  = (const float*)d_in[7];
    float* out = (float*)d_out;

    pos_stats_kernel<<<(HH * NN + 255) / 256, 256>>>(Wpos, bpos);
    qkv_tc_kernel<<<dim3(BB * NN / 128, 12), 256>>>(x, Wqk, Wv);
    pos_scan_kernel<<<BB * HH, 512>>>(Wpos, bpos);
    attn_mma_kernel<<<dim3(NN / 128, HH, BB), 256>>>(gate);
    proj_tc_kernel<<<dim3(BB * NN / 128, 4), 256>>>(Wproj, bproj, out);
}

// round 14
// speedup vs baseline: 3.3301x; 1.1142x over previous
#include <cuda_runtime.h>
#include <cuda_fp16.h>
#include <math.h>

#define BB 2
#define NN 2048
#define CC 256
#define HH 8
#define DHH 32
#define SCALE 0.17677669529663687f  // 1/sqrt(32)
#define CH 256                       // scan chunk size (NN/8)

typedef unsigned long long u64;
typedef unsigned u32;

// ---- scratch ----
__device__ __half g_qh16[BB*HH*NN*DHH];  // [bh][n][d] hi, pre-scaled
__device__ __half g_ql16[BB*HH*NN*DHH];  // lo
__device__ __half g_kh16[BB*HH*NN*DHH];  // [bh][n][d] hi
__device__ __half g_kl16[BB*HH*NN*DHH];
__device__ __half g_vh16[BB*HH*DHH*NN];  // [bh][d][n] hi (transposed)
__device__ __half g_vl16[BB*HH*DHH*NN];
__device__ float g_v [BB*HH*NN*DHH];     // [bh][n][d] f32 (scan input)
__device__ float g_ctx[BB*NN*CC];
__device__ float g_pm[HH*NN];
__device__ float g_pinv[HH*NN];
__device__ float g_scanF[BB*HH*NN*DHH];
__device__ float g_scanG[BB*HH*NN*DHH];

// ---- mma.sync fp16 (sm_80+ PTX; valid at compute_103) ----
__device__ __forceinline__ void mma_f16(float d[4], const u32 a[4], u32 b0, u32 b1) {
    asm volatile(
        "mma.sync.aligned.m16n8k16.row.col.f32.f16.f16.f32 "
        "{%0,%1,%2,%3}, {%4,%5,%6,%7}, {%8,%9}, {%0,%1,%2,%3};"
        : "+f"(d[0]), "+f"(d[1]), "+f"(d[2]), "+f"(d[3])
        : "r"(a[0]), "r"(a[1]), "r"(a[2]), "r"(a[3]), "r"(b0), "r"(b1));
}
__device__ __forceinline__ u32 packh2(float lo, float hi) {
    __half2 v = __floats2half2_rn(lo, hi);
    return *(u32*)&v;
}
__device__ __forceinline__ void split2h(float v0, float v1, u32 &hp, u32 &lp) {
    float h0 = __half2float(__float2half_rn(v0));
    float h1 = __half2float(__float2half_rn(v1));
    hp = packh2(h0, h1);
    lp = packh2(v0 - h0, v1 - h1);
}

// ---- bf16 GEMM helpers (unchanged, for qkv/proj weights path) ----
__device__ __forceinline__ void mma_bf16(float d[4], const u32 a[4], u32 b0, u32 b1) {
    asm volatile(
        "mma.sync.aligned.m16n8k16.row.col.f32.bf16.bf16.f32 "
        "{%0,%1,%2,%3}, {%4,%5,%6,%7}, {%8,%9}, {%0,%1,%2,%3};"
        : "+f"(d[0]), "+f"(d[1]), "+f"(d[2]), "+f"(d[3])
        : "r"(a[0]), "r"(a[1]), "r"(a[2]), "r"(a[3]), "r"(b0), "r"(b1));
}
__device__ __forceinline__ u32 packbf2(float lo, float hi) {
    unsigned short b0, b1;
    asm("cvt.rn.bf16.f32 %0, %1;" : "=h"(b0) : "f"(lo));
    asm("cvt.rn.bf16.f32 %0, %1;" : "=h"(b1) : "f"(hi));
    return (u32)b0 | ((u32)b1 << 16);
}
__device__ __forceinline__ float bf2f(unsigned short b) {
    u32 u = (u32)b << 16;
    return __uint_as_float(u);
}
__device__ __forceinline__ void split2(float v0, float v1, u32 &hp, u32 &lp) {
    u32 hp0 = packbf2(v0, v1);
    float h0 = bf2f((unsigned short)(hp0 & 0xffff));
    float h1 = bf2f((unsigned short)(hp0 >> 16));
    hp = hp0;
    lp = packbf2(v0 - h0, v1 - h1);
}

// ============================================================
// 1) pos softmax row stats, closed form (geometric series)
// ============================================================
__global__ void pos_stats_kernel(const float* __restrict__ Wpos,
                                 const float* __restrict__ bpos) {
    int idx = blockIdx.x * blockDim.x + threadIdx.x;
    if (idx >= HH * NN) return;
    int h = idx / NN, i = idx - h * NN;
    float W0 = Wpos[h], W1 = Wpos[HH + h], bph = bpos[h];
    float apos = W0 + W1;
    float aneg = W1 - W0;
    float fi = (float)i, fM = (float)(NN - 1 - i);
    float mi = fmaxf(0.f, fmaxf(apos * fi, aneg * fM));

    float Sp;
    if (i == 0)            Sp = 0.f;
    else if (apos > 0.f)   Sp = __expf(apos * fi - mi) * expm1f(-apos * fi) / expm1f(-apos);
    else if (apos < 0.f)   Sp = __expf(apos - mi) * expm1f(apos * fi) / expm1f(apos);
    else                   Sp = fi * __expf(-mi);

    float Sn;
    if (i == NN - 1)       Sn = 0.f;
    else if (aneg > 0.f)   Sn = __expf(aneg * fM - mi) * expm1f(-aneg * fM) / expm1f(-aneg);
    else if (aneg < 0.f)   Sn = __expf(aneg - mi) * expm1f(aneg * fM) / expm1f(aneg);
    else                   Sn = fM * __expf(-mi);

    float den = __expf(-mi) + Sp + Sn;
    g_pm[idx]   = bph + mi;
    g_pinv[idx] = 1.f / den;
}

// ============================================================
// 2) QKV GEMM on mma.sync split-bf16 (3-pass); epilogue emits
//    fp16 hi/lo q,k,vT + f32 v.
// ============================================================
__global__ void __launch_bounds__(256) qkv_tc_kernel(const float* __restrict__ x,
                                                     const float* __restrict__ Wqk,
                                                     const float* __restrict__ Wv) {
    __shared__ u32 sAh[128 * 20], sAl[128 * 20];
    __shared__ u32 sBh[64 * 20],  sBl[64 * 20];

    int tid = threadIdx.x;
    int w = tid >> 5, lane = tid & 31, g = lane >> 2, t = lane & 3;
    int m0 = blockIdx.x * 128, n0 = blockIdx.y * 64;

    const float* Wsrc; int ldw, coff;
    if (n0 < 512) { Wsrc = Wqk; ldw = 512; coff = n0; }
    else          { Wsrc = Wv;  ldw = 256; coff = n0 - 512; }

    int arow = tid >> 1, ahalf = tid & 1;
    int bn = tid & 63, bkg = tid >> 6;

    float o[8][4] = {};

    for (int kc = 0; kc < 8; kc++) {
        int k0 = kc * 32;
        __syncthreads();
        {
            const float* xs = &x[(size_t)(m0 + arow) * 256 + k0 + ahalf * 16];
            float4 f0 = *(const float4*)xs, f1 = *(const float4*)(xs + 4);
            float4 f2 = *(const float4*)(xs + 8), f3 = *(const float4*)(xs + 12);
            u32 hi[8], lo[8];
            split2(f0.x, f0.y, hi[0], lo[0]); split2(f0.z, f0.w, hi[1], lo[1]);
            split2(f1.x, f1.y, hi[2], lo[2]); split2(f1.z, f1.w, hi[3], lo[3]);
            split2(f2.x, f2.y, hi[4], lo[4]); split2(f2.z, f2.w, hi[5], lo[5]);
            split2(f3.x, f3.y, hi[6], lo[6]); split2(f3.z, f3.w, hi[7], lo[7]);
            uint4* dh = (uint4*)&sAh[arow * 20 + ahalf * 8];
            dh[0] = make_uint4(hi[0], hi[1], hi[2], hi[3]);
            dh[1] = make_uint4(hi[4], hi[5], hi[6], hi[7]);
            uint4* dl = (uint4*)&sAl[arow * 20 + ahalf * 8];
            dl[0] = make_uint4(lo[0], lo[1], lo[2], lo[3]);
            dl[1] = make_uint4(lo[4], lo[5], lo[6], lo[7]);
        }
        {
            float wv[8];
            #pragma unroll
            for (int i = 0; i < 8; i++)
                wv[i] = Wsrc[(size_t)(k0 + bkg * 8 + i) * ldw + coff + bn];
            u32 bh4[4], bl4[4];
            split2(wv[0], wv[1], bh4[0], bl4[0]);
            split2(wv[2], wv[3], bh4[1], bl4[1]);
            split2(wv[4], wv[5], bh4[2], bl4[2]);
            split2(wv[6], wv[7], bh4[3], bl4[3]);
            *(uint4*)&sBh[bn * 20 + bkg * 4] = make_uint4(bh4[0], bh4[1], bh4[2], bh4[3]);
            *(uint4*)&sBl[bn * 20 + bkg * 4] = make_uint4(bl4[0], bl4[1], bl4[2], bl4[3]);
        }
        __syncthreads();

        u32 aH[2][4], aL[2][4];
        int r0 = 16 * w + g;
        #pragma unroll
        for (int c = 0; c < 2; c++) {
            aH[c][0] = sAh[r0 * 20 + 8 * c + t];
            aH[c][1] = sAh[(r0 + 8) * 20 + 8 * c + t];
            aH[c][2] = sAh[r0 * 20 + 8 * c + t + 4];
            aH[c][3] = sAh[(r0 + 8) * 20 + 8 * c + t + 4];
            aL[c][0] = sAl[r0 * 20 + 8 * c + t];
            aL[c][1] = sAl[(r0 + 8) * 20 + 8 * c + t];
            aL[c][2] = sAl[r0 * 20 + 8 * c + t + 4];
            aL[c][3] = sAl[(r0 + 8) * 20 + 8 * c + t + 4];
        }
        #pragma unroll
        for (int j = 0; j < 8; j++) {
            #pragma unroll
            for (int c = 0; c < 2; c++) {
                int base = (8 * j + g) * 20 + 8 * c + t;
                u32 b0 = sBh[base], b1 = sBh[base + 4];
                u32 c0 = sBl[base], c1 = sBl[base + 4];
                mma_bf16(o[j], aH[c], b0, b1);
                mma_bf16(o[j], aH[c], c0, c1);
                mma_bf16(o[j], aL[c], b0, b1);
            }
        }
    }

    int row_a = m0 + 16 * w + g;
    #pragma unroll
    for (int j = 0; j < 8; j++) {
        int c = n0 + 8 * j + 2 * t;
        #pragma unroll
        for (int r = 0; r < 2; r++) {
            int m = row_a + 8 * r;
            float v0 = o[j][2 * r], v1 = o[j][2 * r + 1];
            int b = m >> 11, n = m & (NN - 1);
            if (c < 256) {
                int h = c >> 5, d0 = c & 31;
                int bh = b * HH + h;
                v0 *= SCALE; v1 *= SCALE;
                u32 hp, lp;
                split2h(v0, v1, hp, lp);
                size_t ui = ((size_t)bh * NN + n) * 16 + (d0 >> 1);
                ((u32*)g_qh16)[ui] = hp;
                ((u32*)g_ql16)[ui] = lp;
            } else if (c < 512) {
                int cc = c - 256; int h = cc >> 5, d0 = cc & 31;
                int bh = b * HH + h;
                u32 hp, lp;
                split2h(v0, v1, hp, lp);
                size_t ui = ((size_t)bh * NN + n) * 16 + (d0 >> 1);
                ((u32*)g_kh16)[ui] = hp;
                ((u32*)g_kl16)[ui] = lp;
            } else {
                int cc = c - 512; int h = cc >> 5, d0 = cc & 31;
                int bh = b * HH + h;
                *(float2*)&g_v[((size_t)bh * NN + n) * DHH + d0] = make_float2(v0, v1);
                __half h0 = __float2half_rn(v0);
                __half h1 = __float2half_rn(v1);
                size_t t0 = ((size_t)bh * DHH + d0) * NN + n;
                g_vh16[t0]      = h0;
                g_vl16[t0]      = __float2half_rn(v0 - __half2float(h0));
                g_vh16[t0 + NN] = h1;
                g_vl16[t0 + NN] = __float2half_rn(v1 - __half2float(h1));
            }
        }
    }
}

// ============================================================
// 3) POS path: blocked-parallel exponential scans, 512 threads
// ============================================================
__global__ void __launch_bounds__(512) pos_scan_kernel(const float* __restrict__ Wpos,
                                                       const float* __restrict__ bpos) {
    __shared__ float TFs[8][32], TGs[8][32], AFs[8][32], DGs[8][32];

    int bh = blockIdx.x;
    int h = bh & (HH - 1);
    int tid = threadIdx.x;
    int w = tid >> 5, lane = tid & 31;
    float apos = Wpos[h] + Wpos[HH + h];
    float aneg = Wpos[HH + h] - Wpos[h];
    bool posg = apos > 0.f, negg = aneg > 0.f;
    float rhoF = posg ? 1.f : __expf(apos);
    float rhoG = negg ? 1.f : __expf(aneg);
    float wcF = posg ? -apos : 0.f;
    float wcG = negg ? -aneg : 0.f;
    float usG = negg ? 1.f : rhoG;

    const float* vp = g_v + (size_t)bh * NN * DHH + lane;
    float* fo = g_scanF + (size_t)bh * NN * DHH + lane;
    float* go = g_scanG + (size_t)bh * NN * DHH + lane;

    if (w < 8) {
        int c0 = w * CH;
        float F = 0.f;
        for (int ib = c0; ib < c0 + CH; ib += 8) {
            float vb[8];
            #pragma unroll
            for (int u = 0; u < 8; u++) vb[u] = vp[(ib + u) * DHH];
            #pragma unroll
            for (int u = 0; u < 8; u++) {
                float uu = vb[u] * __expf(wcF * (float)(ib + u));
                F = rhoF * F + uu;
                fo[(ib + u) * DHH] = F;
            }
        }
        TFs[w][lane] = F;
    } else {
        int c0 = (w - 8) * CH;
        float G = 0.f;
        for (int ib = c0 + CH - 1; ib >= c0; ib -= 8) {
            float vb[8];
            #pragma unroll
            for (int u = 0; u < 8; u++) vb[u] = vp[(ib - u) * DHH];
            #pragma unroll
            for (int u = 0; u < 8; u++) {
                int i = ib - u;
                go[i * DHH] = G;
                float uu = usG * vb[u] * __expf(wcG * (float)(NN - 1 - i));
                G = rhoG * G + uu;
            }
        }
        TGs[w - 8][lane] = G;
    }
    __syncthreads();

    if (w == 0) {
        float fF = posg ? 1.f : __expf(apos * (float)CH);
        float A = 0.f;
        #pragma unroll
        for (int c = 0; c < 8; c++) { AFs[c][lane] = A; A = TFs[c][lane] + fF * A; }
    } else if (w == 8) {
        float fG = negg ? 1.f : __expf(aneg * (float)CH);
        float D = 0.f;
        #pragma unroll
        for (int c = 7; c >= 0; c--) { DGs[c][lane] = D; D = TGs[c][lane] + fG * D; }
    }
    __syncthreads();

    int c = w >> 1;
    int c0 = c * CH;
    int cend = c0 + CH;
    int r0 = w * 128;
    float A = AFs[c][lane];
    float D = DGs[c][lane];
    float pfc = posg ? 0.f : apos;
    float gfc = negg ? 0.f : aneg;
    float bph = bpos[h];
    float pp = fmaxf(apos, 0.f), pn = fmaxf(aneg, 0.f);
    const float* pmrow = g_pm + h * NN;
    for (int ib = r0; ib < r0 + 128; ib += 8) {
        float fb[8], gb[8], pmb[8];
        #pragma unroll
        for (int u = 0; u < 8; u++) {
            fb[u]  = fo[(ib + u) * DHH];
            gb[u]  = go[(ib + u) * DHH];
            pmb[u] = pmrow[ib + u];
        }
        #pragma unroll
        for (int u = 0; u < 8; u++) {
            int i = ib + u;
            float Fg = fb[u] + A * __expf(pfc * (float)(i - c0 + 1));
            float Gg = gb[u] + D * __expf(gfc * (float)(cend - 1 - i));
            float c1 = __expf(bph + pp * (float)i - pmb[u]);
            float c2 = __expf(bph + pn * (float)(NN - 1 - i) - pmb[u]);
            fo[i * DHH] = c1 * Fg + c2 * Gg;
        }
    }
}

// ============================================================
// 4) PATCH attention, fp16 mma.sync:
//    QK 3-pass (full precision), P single-pass fp16, PV 2-pass.
//    K/V double-buffered -> 1 barrier per tile.
// ============================================================
__global__ void __launch_bounds__(256, 2) attn_mma_kernel(const float* __restrict__ gating) {
    __shared__ u32 QsH[128 * 20], QsL[128 * 20];
    __shared__ u32 KsH[2][32 * 20], KsL[2][32 * 20];
    __shared__ u32 VsH[2][32 * 20], VsL[2][32 * 20];

    int tid = threadIdx.x;
    int w = tid >> 5, lane = tid & 31, g = lane >> 2, t = lane & 3;
    int qt = blockIdx.x, hidx = blockIdx.y, b = blockIdx.z;
    int bh = b * HH + hidx;
    int q0 = qt * 128;

    const u32* gqh = (const u32*)g_qh16 + (size_t)bh * NN * 16;
    const u32* gql = (const u32*)g_ql16 + (size_t)bh * NN * 16;
    const u32* gkh = (const u32*)g_kh16 + (size_t)bh * NN * 16;
    const u32* gkl = (const u32*)g_kl16 + (size_t)bh * NN * 16;
    const u32* gvh = (const u32*)g_vh16 + (size_t)bh * DHH * (NN / 2);
    const u32* gvl = (const u32*)g_vl16 + (size_t)bh * DHH * (NN / 2);

    // stage Q [128][32] hi/lo
    {
        int row = tid >> 1, half = tid & 1;
        const uint4* s0 = (const uint4*)(gqh + (size_t)(q0 + row) * 16 + half * 8);
        uint4 v0 = s0[0], v1 = s0[1];
        uint4* d0 = (uint4*)&QsH[row * 20 + half * 8];
        d0[0] = v0; d0[1] = v1;
        const uint4* s1 = (const uint4*)(gql + (size_t)(q0 + row) * 16 + half * 8);
        v0 = s1[0]; v1 = s1[1];
        uint4* d1 = (uint4*)&QsL[row * 20 + half * 8];
        d1[0] = v0; d1[1] = v1;
    }
    // stage K/V tile 0 into buffer 0
    int srow = tid >> 3, spp = tid & 7;
    {
        *(uint2*)&KsH[0][srow * 20 + spp * 2] = *(const uint2*)(gkh + (size_t)srow * 16 + spp * 2);
        *(uint2*)&KsL[0][srow * 20 + spp * 2] = *(const uint2*)(gkl + (size_t)srow * 16 + spp * 2);
        *(uint2*)&VsH[0][srow * 20 + spp * 2] = *(const uint2*)(gvh + (size_t)srow * (NN / 2) + spp * 2);
        *(uint2*)&VsL[0][srow * 20 + spp * 2] = *(const uint2*)(gvl + (size_t)srow * (NN / 2) + spp * 2);
    }
    __syncthreads();

    // Q fragments (constant across tiles)
    u32 aQh[2][4], aQl[2][4];
    {
        int r0 = 16 * w + g;
        #pragma unroll
        for (int c = 0; c < 2; c++) {
            aQh[c][0] = QsH[r0 * 20 + 8 * c + t];
            aQh[c][1] = QsH[(r0 + 8) * 20 + 8 * c + t];
            aQh[c][2] = QsH[r0 * 20 + 8 * c + t + 4];
            aQh[c][3] = QsH[(r0 + 8) * 20 + 8 * c + t + 4];
            aQl[c][0] = QsL[r0 * 20 + 8 * c + t];
            aQl[c][1] = QsL[(r0 + 8) * 20 + 8 * c + t];
            aQl[c][2] = QsL[r0 * 20 + 8 * c + t + 4];
            aQl[c][3] = QsL[(r0 + 8) * 20 + 8 * c + t + 4];
        }
    }

    float o[4][4] = {};
    float lp0 = 0.f, lp1 = 0.f;

    for (int kt = 0; kt < 64; kt++) {
        int buf = kt & 1;
        // prefetch next tile into registers
        uint2 pkh, pkl, pvh, pvl;
        if (kt < 63) {
            int k0n = (kt + 1) * 32;
            pkh = *(const uint2*)(gkh + (size_t)(k0n + srow) * 16 + spp * 2);
            pkl = *(const uint2*)(gkl + (size_t)(k0n + srow) * 16 + spp * 2);
            pvh = *(const uint2*)(gvh + (size_t)srow * (NN / 2) + k0n / 2 + spp * 2);
            pvl = *(const uint2*)(gvl + (size_t)srow * (NN / 2) + k0n / 2 + spp * 2);
        }
        // ---- QK: S[16q x 32k], 3-pass fp16 ----
        float s[4][4] = {};
        #pragma unroll
        for (int j = 0; j < 4; j++) {
            #pragma unroll
            for (int c = 0; c < 2; c++) {
                int base = (8 * j + g) * 20 + 8 * c + t;
                u32 kb0 = KsH[buf][base], kb1 = KsH[buf][base + 4];
                u32 lb0 = KsL[buf][base], lb1 = KsL[buf][base + 4];
                mma_f16(s[j], aQh[c], kb0, kb1);
                mma_f16(s[j], aQh[c], lb0, lb1);
                mma_f16(s[j], aQl[c], kb0, kb1);
            }
        }
        // ---- exp + P fragments (single fp16) ----
        float e[4][4];
        #pragma unroll
        for (int j = 0; j < 4; j++) {
            e[j][0] = __expf(s[j][0]); e[j][1] = __expf(s[j][1]);
            e[j][2] = __expf(s[j][2]); e[j][3] = __expf(s[j][3]);
            lp0 += e[j][0] + e[j][1];
            lp1 += e[j][2] + e[j][3];
        }
        u32 pa[2][4];
        #pragma unroll
        for (int kc = 0; kc < 2; kc++) {
            int j0 = 2 * kc, j1 = 2 * kc + 1;
            pa[kc][0] = packh2(e[j0][0], e[j0][1]);
            pa[kc][1] = packh2(e[j0][2], e[j0][3]);
            pa[kc][2] = packh2(e[j1][0], e[j1][1]);
            pa[kc][3] = packh2(e[j1][2], e[j1][3]);
        }
        // ---- PV: O[16q x 32d], 2-pass (P x Vhi + P x Vlo) ----
        #pragma unroll
        for (int jj = 0; jj < 4; jj++) {
            #pragma unroll
            for (int kc = 0; kc < 2; kc++) {
                int base = (8 * jj + g) * 20 + 8 * kc + t;
                u32 vb0 = VsH[buf][base], vb1 = VsH[buf][base + 4];
                u32 wb0 = VsL[buf][base], wb1 = VsL[buf][base + 4];
                mma_f16(o[jj], pa[kc], vb0, vb1);
                mma_f16(o[jj], pa[kc], wb0, wb1);
            }
        }
        // store prefetch into the other buffer (safe: last read 2 tiles ago)
        if (kt < 63) {
            int nb = buf ^ 1;
            *(uint2*)&KsH[nb][srow * 20 + spp * 2] = pkh;
            *(uint2*)&KsL[nb][srow * 20 + spp * 2] = pkl;
            *(uint2*)&VsH[nb][srow * 20 + spp * 2] = pvh;
            *(uint2*)&VsL[nb][srow * 20 + spp * 2] = pvl;
            __syncthreads();   // single barrier per tile
        }
    }

    // ---- epilogue ----
    lp0 += __shfl_xor_sync(0xffffffffu, lp0, 1);
    lp0 += __shfl_xor_sync(0xffffffffu, lp0, 2);
    lp1 += __shfl_xor_sync(0xffffffffu, lp1, 1);
    lp1 += __shfl_xor_sync(0xffffffffu, lp1, 2);

    float gv = 1.f / (1.f + __expf(-gating[hidx]));
    int row0 = q0 + 16 * w + g, row1 = row0 + 8;
    float s1a = (1.f - gv) / lp0, s1b = (1.f - gv) / lp1;
    float s2a = gv * g_pinv[hidx * NN + row0];
    float s2b = gv * g_pinv[hidx * NN + row1];

    #pragma unroll
    for (int jj = 0; jj < 4; jj++) {
        int dh = 8 * jj + 2 * t;
        float2 p0 = *(const float2*)&g_scanF[((size_t)bh * NN + row0) * DHH + dh];
        float2 p1 = *(const float2*)&g_scanF[((size_t)bh * NN + row1) * DHH + dh];
        float2 o0 = make_float2(s1a * o[jj][0] + s2a * p0.x, s1a * o[jj][1] + s2a * p0.y);
        float2 o1 = make_float2(s1b * o[jj][2] + s2b * p1.x, s1b * o[jj][3] + s2b * p1.y);
        int col = hidx * 32 + dh;
        *(float2*)&g_ctx[((size_t)b * NN + row0) * CC + col] = o0;
        *(float2*)&g_ctx[((size_t)b * NN + row1) * CC + col] = o1;
    }
}

// ============================================================
// 5) Output projection on mma.sync split-bf16 (3-pass)
// ============================================================
__global__ void __launch_bounds__(256) proj_tc_kernel(const float* __restrict__ Wp,
                                                      const float* __restrict__ bp,
                                                      float* __restrict__ out) {
    __shared__ u32 sAh[128 * 20], sAl[128 * 20];
    __shared__ u32 sBh[64 * 20],  sBl[64 * 20];

    int tid = threadIdx.x;
    int w = tid >> 5, lane = tid & 31, g = lane >> 2, t = lane & 3;
    int m0 = blockIdx.x * 128, n0 = blockIdx.y * 64;

    int arow = tid >> 1, ahalf = tid & 1;
    int bn = tid & 63, bkg = tid >> 6;

    float o[8][4] = {};

    for (int kc = 0; kc < 8; kc++) {
        int k0 = kc * 32;
        __syncthreads();
        {
            const float* xs = &g_ctx[(size_t)(m0 + arow) * 256 + k0 + ahalf * 16];
            float4 f0 = *(const float4*)xs, f1 = *(const float4*)(xs + 4);
            float4 f2 = *(const float4*)(xs + 8), f3 = *(const float4*)(xs + 12);
            u32 hi[8], lo[8];
            split2(f0.x, f0.y, hi[0], lo[0]); split2(f0.z, f0.w, hi[1], lo[1]);
            split2(f1.x, f1.y, hi[2], lo[2]); split2(f1.z, f1.w, hi[3], lo[3]);
            split2(f2.x, f2.y, hi[4], lo[4]); split2(f2.z, f2.w, hi[5], lo[5]);
            split2(f3.x, f3.y, hi[6], lo[6]); split2(f3.z, f3.w, hi[7], lo[7]);
            uint4* dh = (uint4*)&sAh[arow * 20 + ahalf * 8];
            dh[0] = make_uint4(hi[0], hi[1], hi[2], hi[3]);
            dh[1] = make_uint4(hi[4], hi[5], hi[6], hi[7]);
            uint4* dl = (uint4*)&sAl[arow * 20 + ahalf * 8];
            dl[0] = make_uint4(lo[0], lo[1], lo[2], lo[3]);
            dl[1] = make_uint4(lo[4], lo[5], lo[6], lo[7]);
        }
        {
            float wv[8];
            #pragma unroll
            for (int i = 0; i < 8; i++)
                wv[i] = Wp[(size_t)(k0 + bkg * 8 + i) * 256 + n0 + bn];
            u32 bh4[4], bl4[4];
            split2(wv[0], wv[1], bh4[0], bl4[0]);
            split2(wv[2], wv[3], bh4[1], bl4[1]);
            split2(wv[4], wv[5], bh4[2], bl4[2]);
            split2(wv[6], wv[7], bh4[3], bl4[3]);
            *(uint4*)&sBh[bn * 20 + bkg * 4] = make_uint4(bh4[0], bh4[1], bh4[2], bh4[3]);
            *(uint4*)&sBl[bn * 20 + bkg * 4] = make_uint4(bl4[0], bl4[1], bl4[2], bl4[3]);
        }
        __syncthreads();

        u32 aH[2][4], aL[2][4];
        int r0 = 16 * w + g;
        #pragma unroll
        for (int c = 0; c < 2; c++) {
            aH[c][0] = sAh[r0 * 20 + 8 * c + t];
            aH[c][1] = sAh[(r0 + 8) * 20 + 8 * c + t];
            aH[c][2] = sAh[r0 * 20 + 8 * c + t + 4];
            aH[c][3] = sAh[(r0 + 8) * 20 + 8 * c + t + 4];
            aL[c][0] = sAl[r0 * 20 + 8 * c + t];
            aL[c][1] = sAl[(r0 + 8) * 20 + 8 * c + t];
            aL[c][2] = sAl[r0 * 20 + 8 * c + t + 4];
            aL[c][3] = sAl[(r0 + 8) * 20 + 8 * c + t + 4];
        }
        #pragma unroll
        for (int j = 0; j < 8; j++) {
            #pragma unroll
            for (int c = 0; c < 2; c++) {
                int base = (8 * j + g) * 20 + 8 * c + t;
                u32 b0 = sBh[base], b1 = sBh[base + 4];
                u32 c0 = sBl[base], c1 = sBl[base + 4];
                mma_bf16(o[j], aH[c], b0, b1);
                mma_bf16(o[j], aH[c], c0, c1);
                mma_bf16(o[j], aL[c], b0, b1);
            }
        }
    }

    int row_a = m0 + 16 * w + g;
    #pragma unroll
    for (int j = 0; j < 8; j++) {
        int c = n0 + 8 * j + 2 * t;
        float2 bpc = *(const float2*)&bp[c];
        #pragma unroll
        for (int r = 0; r < 2; r++) {
            int m = row_a + 8 * r;
            *(float2*)&out[(size_t)m * 256 + c] =
                make_float2(o[j][2 * r] + bpc.x, o[j][2 * r + 1] + bpc.y);
        }
    }
}

// ============================================================
extern "C" void kernel_launch(void* const* d_in, const int* in_sizes, int n_in,
                              void* d_out, int out_size) {
    const float* x     = (const float*)d_in[0];
    const float* Wqk   = (const float*)d_in[1];
    const float* Wv    = (const float*)d_in[2];
    const float* Wproj = (const float*)d_in[3];
    const float* bproj = (const float*)d_in[4];
    const float* Wpos  = (const float*)d_in[5];
    const float* bpos  = (const float*)d_in[6];
    const float* gate  = (const float*)d_in[7];
    float* out = (float*)d_out;

    pos_stats_kernel<<<(HH * NN + 255) / 256, 256>>>(Wpos, bpos);
    qkv_tc_kernel<<<dim3(BB * NN / 128, 12), 256>>>(x, Wqk, Wv);
    pos_scan_kernel<<<BB * HH, 512>>>(Wpos, bpos);
    attn_mma_kernel<<<dim3(NN / 128, HH, BB), 256>>>(gate);
    proj_tc_kernel<<<dim3(BB * NN / 128, 4), 256>>>(Wproj, bproj, out);
}